// round 2
// baseline (speedup 1.0000x reference)
#include <cuda_runtime.h>
#include <math.h>

// ---------------- problem constants ----------------
#define BSZ   8
#define NPT   32          // nodes per batch
#define NEDGE 1024        // N*N edge points
#define NPTS  1056        // 32 nodes + 1024 edges
#define LATC  1536
#define UNIT  512

// ---------------- scratch (__device__ globals, no allocation) ----------------
__device__ float d_A [BSZ * LATC * NPTS];        // aligned features [b][c][pid]
__device__ float d_Gn[BSZ * 2048 * NPT];         // node GEMM: rows [g_i, g_j, p_i, p_j]
__device__ float d_X [BSZ * 1024 * NEDGE];       // intro output (gate rows 0..511, pr 512..1023)
__device__ float d_Y [BSZ * 1024 * NEDGE];       // chorus output
__device__ float d_gate[BSZ * NEDGE];
__device__ float d_pr [BSZ * 64 * NEDGE];

// ---------------- K1: bilinear align at all 1056 points ----------------
// block (32 pids, 8 channel-lanes); grid (33, B)
__global__ void align_kernel(const float* __restrict__ f0, const float* __restrict__ f1,
                             const float* __restrict__ f2, const float* __restrict__ f3,
                             const float* __restrict__ f4, const float* __restrict__ f5,
                             const float* __restrict__ P)
{
    const int pid = blockIdx.x * 32 + threadIdx.x;
    const int b   = blockIdx.y;
    if (pid >= NPTS) return;

    float px, py;
    if (pid < NPT) {
        px = P[(b * NPT + pid) * 2 + 0];
        py = P[(b * NPT + pid) * 2 + 1];
    } else {
        int m = pid - NPT;
        int i = m >> 5, j = m & 31;
        px = 0.5f * (P[(b * NPT + i) * 2 + 0] + P[(b * NPT + j) * 2 + 0]);
        py = 0.5f * (P[(b * NPT + i) * 2 + 1] + P[(b * NPT + j) * 2 + 1]);
    }

    const float* feats[6] = { f0, f1, f2, f3, f4, f5 };
    const int Cs[6] = { 64, 64, 128, 256, 512, 512 };
    const int Hs[6] = { 128, 64, 32, 16, 8, 1 };

    int choff = 0;
    #pragma unroll
    for (int l = 0; l < 6; l++) {
        const int C = Cs[l], H = Hs[l];
        float xs = fminf(fmaxf(px * ((float)H * (1.0f / 256.0f)) - 0.5f, 0.0f), (float)(H - 1));
        float ys = fminf(fmaxf(py * ((float)H * (1.0f / 256.0f)) - 0.5f, 0.0f), (float)(H - 1));
        float x0f = floorf(xs), y0f = floorf(ys);
        float wx = xs - x0f, wy = ys - y0f;
        int x0 = (int)x0f, y0 = (int)y0f;
        int x1 = min(x0 + 1, H - 1), y1 = min(y0 + 1, H - 1);
        float w00 = (1.f - wx) * (1.f - wy);
        float w01 = wx * (1.f - wy);
        float w10 = (1.f - wx) * wy;
        float w11 = wx * wy;
        int i00 = y0 * H + x0, i01 = y0 * H + x1, i10 = y1 * H + x0, i11 = y1 * H + x1;
        const float* f = feats[l];
        const int hw = H * H;
        for (int c = threadIdx.y; c < C; c += 8) {
            const float* base = f + (size_t)(b * C + c) * hw;
            float v = base[i00] * w00 + base[i01] * w01 + base[i10] * w10 + base[i11] * w11;
            d_A[((size_t)b * LATC + choff + c) * NPTS + pid] = v;
        }
        choff += C;
    }
}

// ---------------- K2: node GEMM  Gn[b][r][p] = W_node(r,:) @ F_node + bias ----------------
// rows: [0,512) g_i(+g_ib)  [512,1024) g_j  [1024,1536) p_i(+p_ib)  [1536,2048) p_j
// block (32,8), grid (256, B)
__global__ void node_gemm(const float* __restrict__ g_iw, const float* __restrict__ p_iw,
                          const float* __restrict__ g_ib, const float* __restrict__ p_ib)
{
    const int p = threadIdx.x;
    const int r = blockIdx.x * 8 + threadIdx.y;
    const int b = blockIdx.y;

    const float* w;
    float acc = 0.f;
    if (r < 512)        { w = g_iw + (size_t)r * 4608;                 acc = g_ib[r]; }
    else if (r < 1024)  { w = g_iw + (size_t)(r - 512) * 4608 + 1536; }
    else if (r < 1536)  { w = p_iw + (size_t)(r - 1024) * 4608;        acc = p_ib[r - 1024]; }
    else                { w = p_iw + (size_t)(r - 1536) * 4608 + 1536; }

    const float* Fb = d_A + (size_t)b * LATC * NPTS;
    #pragma unroll 8
    for (int k = 0; k < LATC; k++)
        acc += w[k] * Fb[(size_t)k * NPTS + p];

    d_Gn[((size_t)b * 2048 + r) * NPT + p] = acc;
}

// ---------------- K3: intro GEMM  X = W_E @ E + Gi + Gj ----------------
// 128x128x16 tile, 256 threads, 8x8 micro-tile. grid (8, 8, B)
__global__ void __launch_bounds__(256, 1) intro_gemm(const float* __restrict__ g_iw,
                                                     const float* __restrict__ p_iw)
{
    const int b    = blockIdx.z;
    const int row0 = blockIdx.y * 128;   // combined rows: gate 0..511, pr 512..1023
    const int col0 = blockIdx.x * 128;   // edge points

    __shared__ float As[16][128];
    __shared__ float Bs[16][128];

    const int tid = threadIdx.x;
    const int tx  = tid & 15;   // point group (8 cols each)
    const int ty  = tid >> 4;   // row group (8 rows each)

    const float* Wb = (row0 < 512) ? (g_iw + 3072) : (p_iw + 3072);
    const int rbase = (row0 < 512) ? row0 : (row0 - 512);
    const float* Eb = d_A + (size_t)b * LATC * NPTS + NPT + col0;  // edge cols start at pid 32

    float acc[8][8];
    #pragma unroll
    for (int m = 0; m < 8; m++)
        #pragma unroll
        for (int n = 0; n < 8; n++) acc[m][n] = 0.f;

    for (int k0 = 0; k0 < LATC; k0 += 16) {
        {
            int rr = tid >> 2;
            int kq = (tid & 3) * 4;
            #pragma unroll
            for (int h = 0; h < 2; h++) {
                int row = rr + h * 64;
                float4 v = *(const float4*)(Wb + (size_t)(rbase + row) * 4608 + k0 + kq);
                As[kq + 0][row] = v.x; As[kq + 1][row] = v.y;
                As[kq + 2][row] = v.z; As[kq + 3][row] = v.w;
            }
        }
        {
            #pragma unroll
            for (int h = 0; h < 2; h++) {
                int lin = tid + h * 256;
                int kk = lin >> 5;
                int cq = (lin & 31) * 4;
                float4 v = *(const float4*)(Eb + (size_t)(k0 + kk) * NPTS + cq);
                *(float4*)&Bs[kk][cq] = v;
            }
        }
        __syncthreads();
        #pragma unroll
        for (int k = 0; k < 16; k++) {
            float ra[8], rb[8];
            #pragma unroll
            for (int m = 0; m < 8; m++) ra[m] = As[k][ty * 8 + m];
            #pragma unroll
            for (int n = 0; n < 8; n++) rb[n] = Bs[k][tx * 8 + n];
            #pragma unroll
            for (int m = 0; m < 8; m++)
                #pragma unroll
                for (int n = 0; n < 8; n++)
                    acc[m][n] += ra[m] * rb[n];
        }
        __syncthreads();
    }

    const float* Gb = d_Gn + (size_t)b * 2048 * NPT;
    float* Xb = d_X + (size_t)b * 1024 * NEDGE;
    #pragma unroll
    for (int m = 0; m < 8; m++) {
        int r  = row0 + ty * 8 + m;
        int gi = (r < 512) ? r : (r + 512);    // gate: rows 0..511 ; pr: 1024..1535
        const float* Gi = Gb + (size_t)gi * NPT;
        const float* Gj = Gb + (size_t)(gi + 512) * NPT;
        #pragma unroll
        for (int n = 0; n < 8; n++) {
            int mc = col0 + tx * 8 + n;
            int ii = mc >> 5, jj = mc & 31;
            Xb[(size_t)r * NEDGE + mc] = acc[m][n] + Gi[ii] + Gj[jj];
        }
    }
}

// ---------------- K4: chorus GEMM  Y = X + CW @ relu(BN(X)) + cb ----------------
__global__ void __launch_bounds__(256, 1) chorus_gemm(
                            const float* __restrict__ g_cw, const float* __restrict__ p_cw,
                            const float* __restrict__ g_cb, const float* __restrict__ p_cb,
                            const float* __restrict__ g_bg, const float* __restrict__ g_bb,
                            const float* __restrict__ g_bm, const float* __restrict__ g_bv,
                            const float* __restrict__ p_bg, const float* __restrict__ p_bb,
                            const float* __restrict__ p_bm, const float* __restrict__ p_bv)
{
    const int b    = blockIdx.z;
    const int row0 = blockIdx.y * 128;
    const int col0 = blockIdx.x * 128;
    const int net  = (row0 >= 512);

    const float* CW = net ? p_cw : g_cw;
    const float* CB = net ? p_cb : g_cb;
    const float* BG = net ? p_bg : g_bg;
    const float* BB = net ? p_bb : g_bb;
    const float* BM = net ? p_bm : g_bm;
    const float* BV = net ? p_bv : g_bv;
    const int rbase = row0 & 511;
    const float* Xnet = d_X + ((size_t)b * 1024 + net * 512) * NEDGE + col0;

    __shared__ float As[16][128];
    __shared__ float Bs[16][128];

    const int tid = threadIdx.x;
    const int tx  = tid & 15;
    const int ty  = tid >> 4;

    float acc[8][8];
    #pragma unroll
    for (int m = 0; m < 8; m++)
        #pragma unroll
        for (int n = 0; n < 8; n++) acc[m][n] = 0.f;

    for (int k0 = 0; k0 < 512; k0 += 16) {
        {
            int rr = tid >> 2;
            int kq = (tid & 3) * 4;
            #pragma unroll
            for (int h = 0; h < 2; h++) {
                int row = rr + h * 64;
                float4 v = *(const float4*)(CW + (size_t)(rbase + row) * 512 + k0 + kq);
                As[kq + 0][row] = v.x; As[kq + 1][row] = v.y;
                As[kq + 2][row] = v.z; As[kq + 3][row] = v.w;
            }
        }
        {
            #pragma unroll
            for (int h = 0; h < 2; h++) {
                int lin = tid + h * 256;
                int kk = lin >> 5;
                int cq = (lin & 31) * 4;
                int kg = k0 + kk;
                float sc = BG[kg] * rsqrtf(BV[kg] + 1e-5f);
                float sh = BB[kg] - BM[kg] * sc;
                float4 v = *(const float4*)(Xnet + (size_t)kg * NEDGE + cq);
                v.x = fmaxf(v.x * sc + sh, 0.f);
                v.y = fmaxf(v.y * sc + sh, 0.f);
                v.z = fmaxf(v.z * sc + sh, 0.f);
                v.w = fmaxf(v.w * sc + sh, 0.f);
                *(float4*)&Bs[kk][cq] = v;
            }
        }
        __syncthreads();
        #pragma unroll
        for (int k = 0; k < 16; k++) {
            float ra[8], rb[8];
            #pragma unroll
            for (int m = 0; m < 8; m++) ra[m] = As[k][ty * 8 + m];
            #pragma unroll
            for (int n = 0; n < 8; n++) rb[n] = Bs[k][tx * 8 + n];
            #pragma unroll
            for (int m = 0; m < 8; m++)
                #pragma unroll
                for (int n = 0; n < 8; n++)
                    acc[m][n] += ra[m] * rb[n];
        }
        __syncthreads();
    }

    float* Yb = d_Y + (size_t)b * 1024 * NEDGE;
    const float* Xb = d_X + (size_t)b * 1024 * NEDGE;
    #pragma unroll
    for (int m = 0; m < 8; m++) {
        int r = row0 + ty * 8 + m;
        float cbv = CB[r & 511];
        #pragma unroll
        for (int n = 0; n < 8; n++) {
            int mc = col0 + tx * 8 + n;
            Yb[(size_t)r * NEDGE + mc] = acc[m][n] + Xb[(size_t)r * NEDGE + mc] + cbv;
        }
    }
}

// ---------------- K5: outro  gate_raw / pr_raw = OW @ Y + ob ----------------
// block (64 pts, 8 ocs), grid (16, 9, B); oc 0 = gate, oc 1..64 = pr channels
__global__ void outro_kernel(const float* __restrict__ g_ow, const float* __restrict__ g_ob,
                             const float* __restrict__ p_ow, const float* __restrict__ p_ob)
{
    const int m  = blockIdx.x * 64 + threadIdx.x;
    const int oc = blockIdx.y * 8 + threadIdx.y;
    const int b  = blockIdx.z;
    if (oc >= 65) return;

    const float* Yb = d_Y + (size_t)b * 1024 * NEDGE;
    const float* w;
    const float* ysrc;
    float acc;
    if (oc == 0) { w = g_ow;                        acc = g_ob[0];      ysrc = Yb; }
    else         { w = p_ow + (size_t)(oc - 1) * 512; acc = p_ob[oc - 1]; ysrc = Yb + (size_t)512 * NEDGE; }

    #pragma unroll 8
    for (int r = 0; r < 512; r++)
        acc += w[r] * ysrc[(size_t)r * NEDGE + m];

    if (oc == 0) d_gate[b * NEDGE + m] = acc;
    else         d_pr[((size_t)b * 64 + (oc - 1)) * NEDGE + m] = acc;
}

// ---------------- K6: final  sigmoid(gate) * normalize(pr) * mask ----------------
__global__ void final_kernel(const int* __restrict__ nvec, float* __restrict__ out)
{
    const int m = blockIdx.x * blockDim.x + threadIdx.x;
    const int b = blockIdx.y;
    if (m >= NEDGE) return;
    const int i = m >> 5, j = m & 31;
    const int nb = nvec[b];
    const bool ok = (i < nb) && (j < nb);

    float pv[64];
    float ss = 0.f;
    #pragma unroll
    for (int c = 0; c < 64; c++) {
        pv[c] = d_pr[((size_t)b * 64 + c) * NEDGE + m];
        ss += pv[c] * pv[c];
    }
    float g = 1.f / (1.f + expf(-d_gate[b * NEDGE + m]));
    float s = ok ? (g / fmaxf(sqrtf(ss), 1e-12f)) : 0.f;

    #pragma unroll
    for (int c = 0; c < 64; c++)
        out[((size_t)b * 64 + c) * NEDGE + m] = pv[c] * s;
}

// ---------------- launch ----------------
extern "C" void kernel_launch(void* const* d_in, const int* in_sizes, int n_in,
                              void* d_out, int out_size)
{
    const float* f0 = (const float*)d_in[0];
    const float* f1 = (const float*)d_in[1];
    const float* f2 = (const float*)d_in[2];
    const float* f3 = (const float*)d_in[3];
    const float* f4 = (const float*)d_in[4];
    const float* f5 = (const float*)d_in[5];
    const float* P  = (const float*)d_in[6];
    const int*   nv = (const int*)d_in[7];
    const float* g_iw = (const float*)d_in[8];
    const float* g_ib = (const float*)d_in[9];
    const float* g_bg = (const float*)d_in[10];
    const float* g_bb = (const float*)d_in[11];
    const float* g_bm = (const float*)d_in[12];
    const float* g_bv = (const float*)d_in[13];
    const float* g_cw = (const float*)d_in[14];
    const float* g_cb = (const float*)d_in[15];
    const float* g_ow = (const float*)d_in[16];
    const float* g_ob = (const float*)d_in[17];
    const float* p_iw = (const float*)d_in[18];
    const float* p_ib = (const float*)d_in[19];
    const float* p_bg = (const float*)d_in[20];
    const float* p_bb = (const float*)d_in[21];
    const float* p_bm = (const float*)d_in[22];
    const float* p_bv = (const float*)d_in[23];
    const float* p_cw = (const float*)d_in[24];
    const float* p_cb = (const float*)d_in[25];
    const float* p_ow = (const float*)d_in[26];
    const float* p_ob = (const float*)d_in[27];
    float* out = (float*)d_out;

    align_kernel<<<dim3(33, BSZ), dim3(32, 8)>>>(f0, f1, f2, f3, f4, f5, P);
    node_gemm   <<<dim3(256, BSZ), dim3(32, 8)>>>(g_iw, p_iw, g_ib, p_ib);
    intro_gemm  <<<dim3(8, 8, BSZ), 256>>>(g_iw, p_iw);
    chorus_gemm <<<dim3(8, 8, BSZ), 256>>>(g_cw, p_cw, g_cb, p_cb,
                                           g_bg, g_bb, g_bm, g_bv,
                                           p_bg, p_bb, p_bm, p_bv);
    outro_kernel<<<dim3(16, 9, BSZ), dim3(64, 8)>>>(g_ow, g_ob, p_ow, p_ob);
    final_kernel<<<dim3(4, BSZ), 256>>>(nv, out);
}

// round 6
// speedup vs baseline: 1.5906x; 1.5906x over previous
#include <cuda_runtime.h>
#include <cuda_bf16.h>
#include <math.h>
#include <stdint.h>

// ---------------- problem constants ----------------
#define BSZ   8
#define NPT   32
#define NEDGE 1024
#define NPTS  1056
#define LATC  1536

// smem layout for gemm_mma (in uint32 words)
#define AH_OFF 0
#define AL_OFF (128 * 20)
#define BH_OFF (2 * 128 * 20)
#define BL_OFF (2 * 128 * 20 + 16 * 136)
#define SMEM_WORDS (2 * 128 * 20 + 2 * 16 * 136)

// ---------------- scratch (__device__ globals) ----------------
__device__ float d_A [BSZ * LATC * NPTS];   // aligned features [b][c][pid]
__device__ float d_Gn[BSZ * 2048 * NPT];    // node GEMM rows [g_i, g_j, p_i, p_j]
__device__ float d_X [BSZ * 1024 * NEDGE];  // intro output
__device__ float d_Y [BSZ * 1024 * NEDGE];  // chorus output
__device__ float d_gate[BSZ * NEDGE];
__device__ float d_pr [BSZ * 64 * NEDGE];

// ---------------- helpers ----------------
__device__ __forceinline__ void split_pair(float x, float y, uint32_t& hp, uint32_t& lp) {
    __nv_bfloat16 hx = __float2bfloat16_rn(x), hy = __float2bfloat16_rn(y);
    __nv_bfloat16 lx = __float2bfloat16_rn(x - __bfloat162float(hx));
    __nv_bfloat16 ly = __float2bfloat16_rn(y - __bfloat162float(hy));
    __nv_bfloat162 h2(hx, hy), l2(lx, ly);
    hp = *reinterpret_cast<uint32_t*>(&h2);
    lp = *reinterpret_cast<uint32_t*>(&l2);
}

__device__ __forceinline__ void mma16816(float* c, const uint32_t* a, const uint32_t* b) {
    asm volatile("mma.sync.aligned.m16n8k16.row.col.f32.bf16.bf16.f32 "
                 "{%0,%1,%2,%3}, {%4,%5,%6,%7}, {%8,%9}, {%0,%1,%2,%3};"
                 : "+f"(c[0]), "+f"(c[1]), "+f"(c[2]), "+f"(c[3])
                 : "r"(a[0]), "r"(a[1]), "r"(a[2]), "r"(a[3]),
                   "r"(b[0]), "r"(b[1]));
}

// ---------------- K1: bilinear align at all 1056 points ----------------
__global__ void align_kernel(const float* __restrict__ f0, const float* __restrict__ f1,
                             const float* __restrict__ f2, const float* __restrict__ f3,
                             const float* __restrict__ f4, const float* __restrict__ f5,
                             const float* __restrict__ P)
{
    const int pid = blockIdx.x * 32 + threadIdx.x;
    const int b   = blockIdx.y;
    if (pid >= NPTS) return;

    float px, py;
    if (pid < NPT) {
        px = P[(b * NPT + pid) * 2 + 0];
        py = P[(b * NPT + pid) * 2 + 1];
    } else {
        int m = pid - NPT;
        int i = m >> 5, j = m & 31;
        px = 0.5f * (P[(b * NPT + i) * 2 + 0] + P[(b * NPT + j) * 2 + 0]);
        py = 0.5f * (P[(b * NPT + i) * 2 + 1] + P[(b * NPT + j) * 2 + 1]);
    }

    const float* feats[6] = { f0, f1, f2, f3, f4, f5 };
    const int Cs[6] = { 64, 64, 128, 256, 512, 512 };
    const int Hs[6] = { 128, 64, 32, 16, 8, 1 };

    int choff = 0;
    #pragma unroll
    for (int l = 0; l < 6; l++) {
        const int C = Cs[l], H = Hs[l];
        float xs = fminf(fmaxf(px * ((float)H * (1.0f / 256.0f)) - 0.5f, 0.0f), (float)(H - 1));
        float ys = fminf(fmaxf(py * ((float)H * (1.0f / 256.0f)) - 0.5f, 0.0f), (float)(H - 1));
        float x0f = floorf(xs), y0f = floorf(ys);
        float wx = xs - x0f, wy = ys - y0f;
        int x0 = (int)x0f, y0 = (int)y0f;
        int x1 = min(x0 + 1, H - 1), y1 = min(y0 + 1, H - 1);
        float w00 = (1.f - wx) * (1.f - wy);
        float w01 = wx * (1.f - wy);
        float w10 = (1.f - wx) * wy;
        float w11 = wx * wy;
        int i00 = y0 * H + x0, i01 = y0 * H + x1, i10 = y1 * H + x0, i11 = y1 * H + x1;
        const float* f = feats[l];
        const int hw = H * H;
        for (int c = threadIdx.y; c < C; c += 8) {
            const float* base = f + (size_t)(b * C + c) * hw;
            float v = base[i00] * w00 + base[i01] * w01 + base[i10] * w10 + base[i11] * w11;
            d_A[((size_t)b * LATC + choff + c) * NPTS + pid] = v;
        }
        choff += C;
    }
}

// ---------------- K2: node GEMM (tiny, fp32) ----------------
__global__ void node_gemm(const float* __restrict__ g_iw, const float* __restrict__ p_iw,
                          const float* __restrict__ g_ib, const float* __restrict__ p_ib)
{
    const int p = threadIdx.x;
    const int r = blockIdx.x * 8 + threadIdx.y;
    const int b = blockIdx.y;

    const float* w;
    float acc = 0.f;
    if (r < 512)        { w = g_iw + (size_t)r * 4608;                 acc = g_ib[r]; }
    else if (r < 1024)  { w = g_iw + (size_t)(r - 512) * 4608 + 1536; }
    else if (r < 1536)  { w = p_iw + (size_t)(r - 1024) * 4608;        acc = p_ib[r - 1024]; }
    else                { w = p_iw + (size_t)(r - 1536) * 4608 + 1536; }

    const float* Fb = d_A + (size_t)b * LATC * NPTS;
    #pragma unroll 8
    for (int k = 0; k < LATC; k++)
        acc += w[k] * Fb[(size_t)k * NPTS + p];

    d_Gn[((size_t)b * 2048 + r) * NPT + p] = acc;
}

// ---------------- HMMA GEMM: C[128x128] = A[128xK] @ B[KxN] ----------------
// A: weights row-major [512][astride] per net. B: [k][n] fp32 source (d_A edges or d_X).
// 3-pass bf16 hi/lo split, fp32 accum.
// MODE 0 (intro):  X = D + Gi + Gj        (B = d_A edges, shared across nets)
// MODE 1 (chorus): Y = D + X + cb         (B = relu(BN(X)) per net, fused in loader)
template<int KTOT, int MODE>
__global__ void __launch_bounds__(256) gemm_mma(
    const float* __restrict__ Wg, const float* __restrict__ Wp, int astride,
    const float* __restrict__ g_bg, const float* __restrict__ g_bb,
    const float* __restrict__ g_bm, const float* __restrict__ g_bv,
    const float* __restrict__ p_bg, const float* __restrict__ p_bb,
    const float* __restrict__ p_bm, const float* __restrict__ p_bv,
    const float* __restrict__ g_cb, const float* __restrict__ p_cb)
{
    // A tiles: [128 rows][16 k2] u32, row stride 20; B tiles: [16 k2][128 n] u32, stride 136
    extern __shared__ uint32_t smw[];
    uint32_t* Ah_s = smw + AH_OFF;
    uint32_t* Al_s = smw + AL_OFF;
    uint32_t* Bh_s = smw + BH_OFF;
    uint32_t* Bl_s = smw + BL_OFF;

    const int tid  = threadIdx.x;
    const int lane = tid & 31, wid = tid >> 5;
    const int wm = wid >> 2, wn = wid & 3;            // 2 x 4 warp grid
    const int b    = blockIdx.z;
    const int row0 = blockIdx.y * 128;                // 0..1023 combined rows
    const int col0 = blockIdx.x * 128;
    const int net  = row0 >> 9;
    const int rbase = row0 & 511;

    const float* Ag = (net ? Wp : Wg) + (size_t)rbase * astride;
    const float* Bg;
    int bstride;
    if (MODE == 0) { Bg = d_A + (size_t)b * LATC * NPTS + NPT + col0; bstride = NPTS; }
    else           { Bg = d_X + ((size_t)b * 1024 + net * 512) * NEDGE + col0; bstride = NEDGE; }

    const float* BG = net ? p_bg : g_bg;
    const float* BB = net ? p_bb : g_bb;
    const float* BM = net ? p_bm : g_bm;
    const float* BV = net ? p_bv : g_bv;

    float acc[4][4][4];
    #pragma unroll
    for (int i = 0; i < 4; i++)
        #pragma unroll
        for (int j = 0; j < 4; j++)
            #pragma unroll
            for (int v = 0; v < 4; v++) acc[i][j][v] = 0.f;

    #pragma unroll 1
    for (int k0 = 0; k0 < KTOT; k0 += 32) {
        // ---- load A chunk: 128 rows x 32 k ----
        #pragma unroll
        for (int i = 0; i < 4; i++) {
            int t = tid + i * 256;
            int row = t >> 3, k4 = t & 7;
            float4 v = *(const float4*)(Ag + (size_t)row * astride + k0 + k4 * 4);
            uint32_t hp0, lp0, hp1, lp1;
            split_pair(v.x, v.y, hp0, lp0);
            split_pair(v.z, v.w, hp1, lp1);
            int o = row * 20 + 2 * k4;
            Ah_s[o] = hp0; Ah_s[o + 1] = hp1;
            Al_s[o] = lp0; Al_s[o + 1] = lp1;
        }
        // ---- load B chunk: 32 k x 128 n, pack k-pairs ----
        #pragma unroll
        for (int i = 0; i < 2; i++) {
            int t = tid + i * 256;
            int k2 = t >> 5, n4 = t & 31;
            int k = k0 + 2 * k2;
            float4 v0 = *(const float4*)(Bg + (size_t)k * bstride + n4 * 4);
            float4 v1 = *(const float4*)(Bg + (size_t)(k + 1) * bstride + n4 * 4);
            if (MODE == 1) {
                float sc0 = BG[k] * rsqrtf(BV[k] + 1e-5f);
                float sh0 = BB[k] - BM[k] * sc0;
                float sc1 = BG[k + 1] * rsqrtf(BV[k + 1] + 1e-5f);
                float sh1 = BB[k + 1] - BM[k + 1] * sc1;
                v0.x = fmaxf(v0.x * sc0 + sh0, 0.f); v0.y = fmaxf(v0.y * sc0 + sh0, 0.f);
                v0.z = fmaxf(v0.z * sc0 + sh0, 0.f); v0.w = fmaxf(v0.w * sc0 + sh0, 0.f);
                v1.x = fmaxf(v1.x * sc1 + sh1, 0.f); v1.y = fmaxf(v1.y * sc1 + sh1, 0.f);
                v1.z = fmaxf(v1.z * sc1 + sh1, 0.f); v1.w = fmaxf(v1.w * sc1 + sh1, 0.f);
            }
            uint32_t h[4], l[4];
            split_pair(v0.x, v1.x, h[0], l[0]);
            split_pair(v0.y, v1.y, h[1], l[1]);
            split_pair(v0.z, v1.z, h[2], l[2]);
            split_pair(v0.w, v1.w, h[3], l[3]);
            int o = k2 * 136 + n4 * 4;
            *(uint4*)&Bh_s[o] = make_uint4(h[0], h[1], h[2], h[3]);
            *(uint4*)&Bl_s[o] = make_uint4(l[0], l[1], l[2], l[3]);
        }
        __syncthreads();

        // ---- compute: 2 k16-steps ----
        #pragma unroll
        for (int s = 0; s < 2; s++) {
            const int sb = s * 8;
            const int k2a = sb + (lane & 3);
            uint32_t bh[4][2], bl[4][2];
            #pragma unroll
            for (int nf = 0; nf < 4; nf++) {
                int n = wn * 32 + nf * 8 + (lane >> 2);
                bh[nf][0] = Bh_s[k2a * 136 + n];
                bh[nf][1] = Bh_s[(k2a + 4) * 136 + n];
                bl[nf][0] = Bl_s[k2a * 136 + n];
                bl[nf][1] = Bl_s[(k2a + 4) * 136 + n];
            }
            #pragma unroll
            for (int mf = 0; mf < 4; mf++) {
                int row = wm * 64 + mf * 16 + (lane >> 2);
                uint32_t ah[4], al[4];
                ah[0] = Ah_s[row * 20 + k2a];       ah[1] = Ah_s[(row + 8) * 20 + k2a];
                ah[2] = Ah_s[row * 20 + k2a + 4];   ah[3] = Ah_s[(row + 8) * 20 + k2a + 4];
                al[0] = Al_s[row * 20 + k2a];       al[1] = Al_s[(row + 8) * 20 + k2a];
                al[2] = Al_s[row * 20 + k2a + 4];   al[3] = Al_s[(row + 8) * 20 + k2a + 4];
                #pragma unroll
                for (int nf = 0; nf < 4; nf++) {
                    mma16816(acc[mf][nf], ah, bh[nf]);
                    mma16816(acc[mf][nf], ah, bl[nf]);
                    mma16816(acc[mf][nf], al, bh[nf]);
                }
            }
        }
        __syncthreads();
    }

    // ---- epilogue ----
    #pragma unroll
    for (int mf = 0; mf < 4; mf++) {
        int row_g = row0 + wm * 64 + mf * 16 + (lane >> 2);   // combined row 0..1023
        size_t obase = ((size_t)b * 1024 + row_g) * NEDGE;
        #pragma unroll
        for (int nf = 0; nf < 4; nf++) {
            int colg = col0 + wn * 32 + nf * 8 + (lane & 3) * 2;
            float* a = acc[mf][nf];
            if (MODE == 0) {
                int gir = b * 2048 + row_g + net * 512;
                int gjr = gir + 512;
                int ii = colg >> 5, jj = colg & 31;
                float Gi0 = d_Gn[(size_t)gir * NPT + ii];
                float Gi8 = d_Gn[(size_t)(gir + 8) * NPT + ii];
                float2 w0 = make_float2(a[0] + Gi0 + d_Gn[(size_t)gjr * NPT + jj],
                                        a[1] + Gi0 + d_Gn[(size_t)gjr * NPT + jj + 1]);
                float2 w1 = make_float2(a[2] + Gi8 + d_Gn[(size_t)(gjr + 8) * NPT + jj],
                                        a[3] + Gi8 + d_Gn[(size_t)(gjr + 8) * NPT + jj + 1]);
                *(float2*)&d_X[obase + colg] = w0;
                *(float2*)&d_X[obase + 8 * NEDGE + colg] = w1;
            } else {
                int r = row_g & 511;
                const float* CB = net ? p_cb : g_cb;
                float cb0 = CB[r], cb8 = CB[r + 8];
                float2 x0 = *(const float2*)&d_X[obase + colg];
                float2 x1 = *(const float2*)&d_X[obase + 8 * NEDGE + colg];
                float2 w0 = make_float2(a[0] + x0.x + cb0, a[1] + x0.y + cb0);
                float2 w1 = make_float2(a[2] + x1.x + cb8, a[3] + x1.y + cb8);
                *(float2*)&d_Y[obase + colg] = w0;
                *(float2*)&d_Y[obase + 8 * NEDGE + colg] = w1;
            }
        }
    }
}

// ---------------- K5: outro ----------------
__global__ void outro_kernel(const float* __restrict__ g_ow, const float* __restrict__ g_ob,
                             const float* __restrict__ p_ow, const float* __restrict__ p_ob)
{
    const int m  = blockIdx.x * 64 + threadIdx.x;
    const int oc = blockIdx.y * 8 + threadIdx.y;
    const int b  = blockIdx.z;
    if (oc >= 65) return;

    const float* Yb = d_Y + (size_t)b * 1024 * NEDGE;
    const float* w;
    const float* ysrc;
    float acc;
    if (oc == 0) { w = g_ow;                          acc = g_ob[0];       ysrc = Yb; }
    else         { w = p_ow + (size_t)(oc - 1) * 512; acc = p_ob[oc - 1];  ysrc = Yb + (size_t)512 * NEDGE; }

    #pragma unroll 8
    for (int r = 0; r < 512; r++)
        acc += w[r] * ysrc[(size_t)r * NEDGE + m];

    if (oc == 0) d_gate[b * NEDGE + m] = acc;
    else         d_pr[((size_t)b * 64 + (oc - 1)) * NEDGE + m] = acc;
}

// ---------------- K6: final ----------------
__global__ void final_kernel(const int* __restrict__ nvec, float* __restrict__ out)
{
    const int m = blockIdx.x * blockDim.x + threadIdx.x;
    const int b = blockIdx.y;
    if (m >= NEDGE) return;
    const int i = m >> 5, j = m & 31;
    const int nb = nvec[b];
    const bool ok = (i < nb) && (j < nb);

    float pv[64];
    float ss = 0.f;
    #pragma unroll
    for (int c = 0; c < 64; c++) {
        pv[c] = d_pr[((size_t)b * 64 + c) * NEDGE + m];
        ss += pv[c] * pv[c];
    }
    float g = 1.f / (1.f + expf(-d_gate[b * NEDGE + m]));
    float s = ok ? (g / fmaxf(sqrtf(ss), 1e-12f)) : 0.f;

    #pragma unroll
    for (int c = 0; c < 64; c++)
        out[((size_t)b * 64 + c) * NEDGE + m] = pv[c] * s;
}

// ---------------- launch ----------------
extern "C" void kernel_launch(void* const* d_in, const int* in_sizes, int n_in,
                              void* d_out, int out_size)
{
    const float* f0 = (const float*)d_in[0];
    const float* f1 = (const float*)d_in[1];
    const float* f2 = (const float*)d_in[2];
    const float* f3 = (const float*)d_in[3];
    const float* f4 = (const float*)d_in[4];
    const float* f5 = (const float*)d_in[5];
    const float* P  = (const float*)d_in[6];
    const int*   nv = (const int*)d_in[7];
    const float* g_iw = (const float*)d_in[8];
    const float* g_ib = (const float*)d_in[9];
    const float* g_bg = (const float*)d_in[10];
    const float* g_bb = (const float*)d_in[11];
    const float* g_bm = (const float*)d_in[12];
    const float* g_bv = (const float*)d_in[13];
    const float* g_cw = (const float*)d_in[14];
    const float* g_cb = (const float*)d_in[15];
    const float* g_ow = (const float*)d_in[16];
    const float* g_ob = (const float*)d_in[17];
    const float* p_iw = (const float*)d_in[18];
    const float* p_ib = (const float*)d_in[19];
    const float* p_bg = (const float*)d_in[20];
    const float* p_bb = (const float*)d_in[21];
    const float* p_bm = (const float*)d_in[22];
    const float* p_bv = (const float*)d_in[23];
    const float* p_cw = (const float*)d_in[24];
    const float* p_cb = (const float*)d_in[25];
    const float* p_ow = (const float*)d_in[26];
    const float* p_ob = (const float*)d_in[27];
    float* out = (float*)d_out;

    const int SMEM_BYTES = SMEM_WORDS * 4;   // 58368 B
    cudaFuncSetAttribute(gemm_mma<LATC, 0>, cudaFuncAttributeMaxDynamicSharedMemorySize, SMEM_BYTES);
    cudaFuncSetAttribute(gemm_mma<512, 1>,  cudaFuncAttributeMaxDynamicSharedMemorySize, SMEM_BYTES);

    align_kernel<<<dim3(33, BSZ), dim3(32, 8)>>>(f0, f1, f2, f3, f4, f5, P);
    node_gemm   <<<dim3(256, BSZ), dim3(32, 8)>>>(g_iw, p_iw, g_ib, p_ib);

    // intro: A = E-part of iw (offset 3072, stride 4608), B = d_A edges
    gemm_mma<LATC, 0><<<dim3(8, 8, BSZ), 256, SMEM_BYTES>>>(
        g_iw + 3072, p_iw + 3072, 4608,
        nullptr, nullptr, nullptr, nullptr,
        nullptr, nullptr, nullptr, nullptr,
        nullptr, nullptr);

    // chorus: A = cw (stride 512), B = relu(BN(X)) fused
    gemm_mma<512, 1><<<dim3(8, 8, BSZ), 256, SMEM_BYTES>>>(
        g_cw, p_cw, 512,
        g_bg, g_bb, g_bm, g_bv,
        p_bg, p_bb, p_bm, p_bv,
        g_cb, p_cb);

    outro_kernel<<<dim3(16, 9, BSZ), dim3(64, 8)>>>(g_ow, g_ob, p_ow, p_ob);
    final_kernel<<<dim3(4, BSZ), 256>>>(nv, out);
}

// round 7
// speedup vs baseline: 1.7226x; 1.0830x over previous
#include <cuda_runtime.h>
#include <cuda_bf16.h>
#include <math.h>
#include <stdint.h>

// ---------------- problem constants ----------------
#define BSZ   8
#define NPT   32
#define NEDGE 1024
#define NPTS  1056
#define LATC  1536

// ---------------- gemm smem layout (u32 words) ----------------
#define A_WORDS (128 * 20)
#define B_WORDS (16 * 136)
#define BUF_WORDS (2 * A_WORDS + 2 * B_WORDS)     // Ah, Al, Bh, Bl
#define AH_O 0
#define AL_O A_WORDS
#define BH_O (2 * A_WORDS)
#define BL_O (2 * A_WORDS + B_WORDS)
#define GEMM_SMEM_BYTES (2 * BUF_WORDS * 4)       // 75776 B

// ---------------- scratch (__device__ globals) ----------------
__device__ float d_A [BSZ * LATC * NPTS];   // aligned features [b][c][pid]
__device__ float d_Gn[BSZ * 2048 * NPT];    // node GEMM rows [g_i, g_j, p_i, p_j]
__device__ float d_X [BSZ * 1024 * NEDGE];  // intro output
__device__ float d_Y [BSZ * 1024 * NEDGE];  // chorus output
__device__ float d_gate[BSZ * NEDGE];
__device__ float d_pr [BSZ * 64 * NEDGE];

// packed bf16 k-pair operands (u32 = (bf16 k, bf16 k+1)); hi / lo split
__device__ __align__(16) uint32_t d_WIh[2 * 512 * 768];   // intro E-weights [net*512+r][k2]
__device__ __align__(16) uint32_t d_WIl[2 * 512 * 768];
__device__ __align__(16) uint32_t d_CWh[2 * 512 * 256];   // chorus weights
__device__ __align__(16) uint32_t d_CWl[2 * 512 * 256];
__device__ __align__(16) uint32_t d_Eph[BSZ * 768 * 1024];  // E [b][k2][n]
__device__ __align__(16) uint32_t d_Epl[BSZ * 768 * 1024];
__device__ __align__(16) uint32_t d_Xph[BSZ * 2 * 256 * 1024]; // relu(BN(X)) [z][k2][n]
__device__ __align__(16) uint32_t d_Xpl[BSZ * 2 * 256 * 1024];

// ---------------- helpers ----------------
__device__ __forceinline__ void split_pair(float x, float y, uint32_t& hp, uint32_t& lp) {
    __nv_bfloat16 hx = __float2bfloat16_rn(x), hy = __float2bfloat16_rn(y);
    __nv_bfloat16 lx = __float2bfloat16_rn(x - __bfloat162float(hx));
    __nv_bfloat16 ly = __float2bfloat16_rn(y - __bfloat162float(hy));
    __nv_bfloat162 h2(hx, hy), l2(lx, ly);
    hp = *reinterpret_cast<uint32_t*>(&h2);
    lp = *reinterpret_cast<uint32_t*>(&l2);
}

__device__ __forceinline__ void mma16816(float* c, const uint32_t* a, const uint32_t* b) {
    asm volatile("mma.sync.aligned.m16n8k16.row.col.f32.bf16.bf16.f32 "
                 "{%0,%1,%2,%3}, {%4,%5,%6,%7}, {%8,%9}, {%0,%1,%2,%3};"
                 : "+f"(c[0]), "+f"(c[1]), "+f"(c[2]), "+f"(c[3])
                 : "r"(a[0]), "r"(a[1]), "r"(a[2]), "r"(a[3]),
                   "r"(b[0]), "r"(b[1]));
}

__device__ __forceinline__ uint32_t smem_u32(const void* p) {
    uint32_t a;
    asm("{ .reg .u64 t; cvta.to.shared.u64 t, %1; cvt.u32.u64 %0, t; }" : "=r"(a) : "l"(p));
    return a;
}
__device__ __forceinline__ void cpa16(uint32_t dst_s, const void* src) {
    asm volatile("cp.async.cg.shared.global [%0], [%1], 16;" :: "r"(dst_s), "l"(src));
}

// ---------------- K1: bilinear align at all 1056 points ----------------
__global__ void align_kernel(const float* __restrict__ f0, const float* __restrict__ f1,
                             const float* __restrict__ f2, const float* __restrict__ f3,
                             const float* __restrict__ f4, const float* __restrict__ f5,
                             const float* __restrict__ P)
{
    const int pid = blockIdx.x * 32 + threadIdx.x;
    const int b   = blockIdx.y;
    if (pid >= NPTS) return;

    float px, py;
    if (pid < NPT) {
        px = P[(b * NPT + pid) * 2 + 0];
        py = P[(b * NPT + pid) * 2 + 1];
    } else {
        int m = pid - NPT;
        int i = m >> 5, j = m & 31;
        px = 0.5f * (P[(b * NPT + i) * 2 + 0] + P[(b * NPT + j) * 2 + 0]);
        py = 0.5f * (P[(b * NPT + i) * 2 + 1] + P[(b * NPT + j) * 2 + 1]);
    }

    const float* feats[6] = { f0, f1, f2, f3, f4, f5 };
    const int Cs[6] = { 64, 64, 128, 256, 512, 512 };
    const int Hs[6] = { 128, 64, 32, 16, 8, 1 };

    int choff = 0;
    #pragma unroll
    for (int l = 0; l < 6; l++) {
        const int C = Cs[l], H = Hs[l];
        float xs = fminf(fmaxf(px * ((float)H * (1.0f / 256.0f)) - 0.5f, 0.0f), (float)(H - 1));
        float ys = fminf(fmaxf(py * ((float)H * (1.0f / 256.0f)) - 0.5f, 0.0f), (float)(H - 1));
        float x0f = floorf(xs), y0f = floorf(ys);
        float wx = xs - x0f, wy = ys - y0f;
        int x0 = (int)x0f, y0 = (int)y0f;
        int x1 = min(x0 + 1, H - 1), y1 = min(y0 + 1, H - 1);
        float w00 = (1.f - wx) * (1.f - wy);
        float w01 = wx * (1.f - wy);
        float w10 = (1.f - wx) * wy;
        float w11 = wx * wy;
        int i00 = y0 * H + x0, i01 = y0 * H + x1, i10 = y1 * H + x0, i11 = y1 * H + x1;
        const float* f = feats[l];
        const int hw = H * H;
        for (int c = threadIdx.y; c < C; c += 8) {
            const float* base = f + (size_t)(b * C + c) * hw;
            float v = base[i00] * w00 + base[i01] * w01 + base[i10] * w10 + base[i11] * w11;
            d_A[((size_t)b * LATC + choff + c) * NPTS + pid] = v;
        }
        choff += C;
    }
}

// ---------------- K2: node GEMM (tiny, fp32) ----------------
__global__ void node_gemm(const float* __restrict__ g_iw, const float* __restrict__ p_iw,
                          const float* __restrict__ g_ib, const float* __restrict__ p_ib)
{
    const int p = threadIdx.x;
    const int r = blockIdx.x * 8 + threadIdx.y;
    const int b = blockIdx.y;

    const float* w;
    float acc = 0.f;
    if (r < 512)        { w = g_iw + (size_t)r * 4608;                 acc = g_ib[r]; }
    else if (r < 1024)  { w = g_iw + (size_t)(r - 512) * 4608 + 1536; }
    else if (r < 1536)  { w = p_iw + (size_t)(r - 1024) * 4608;        acc = p_ib[r - 1024]; }
    else                { w = p_iw + (size_t)(r - 1536) * 4608 + 1536; }

    const float* Fb = d_A + (size_t)b * LATC * NPTS;
    #pragma unroll 8
    for (int k = 0; k < LATC; k++)
        acc += w[k] * Fb[(size_t)k * NPTS + p];

    d_Gn[((size_t)b * 2048 + r) * NPT + p] = acc;
}

// ---------------- conversion kernels ----------------
__global__ void convWI(const float* __restrict__ g_iw, const float* __restrict__ p_iw)
{
    int idx = blockIdx.x * 256 + threadIdx.x;       // 2*512*768
    int k2 = idx % 768;
    int r  = (idx / 768) & 511;
    int net = idx / (512 * 768);
    const float* w = (net ? p_iw : g_iw) + (size_t)r * 4608 + 3072 + 2 * k2;
    split_pair(w[0], w[1], d_WIh[idx], d_WIl[idx]);
}

__global__ void convWC(const float* __restrict__ g_cw, const float* __restrict__ p_cw)
{
    int idx = blockIdx.x * 256 + threadIdx.x;       // 2*512*256
    int k2 = idx & 255;
    int r  = (idx >> 8) & 511;
    int net = idx >> 17;
    const float* w = (net ? p_cw : g_cw) + (size_t)r * 512 + 2 * k2;
    split_pair(w[0], w[1], d_CWh[idx], d_CWl[idx]);
}

__global__ void convE()
{
    int idx = blockIdx.x * 256 + threadIdx.x;       // 8*768*1024
    int n  = idx & 1023;
    int t  = idx >> 10;
    int k2 = t % 768;
    int b  = t / 768;
    const float* src = d_A + ((size_t)b * LATC + 2 * k2) * NPTS + NPT + n;
    split_pair(src[0], src[NPTS], d_Eph[idx], d_Epl[idx]);
}

__global__ void convX(const float* __restrict__ g_bg, const float* __restrict__ g_bb,
                      const float* __restrict__ g_bm, const float* __restrict__ g_bv,
                      const float* __restrict__ p_bg, const float* __restrict__ p_bb,
                      const float* __restrict__ p_bm, const float* __restrict__ p_bv)
{
    int idx = blockIdx.x * 256 + threadIdx.x;       // 8*2*256*1024
    int n  = idx & 1023;
    int t  = idx >> 10;
    int k2 = t & 255;
    int z  = t >> 8;
    int b = z >> 1, net = z & 1;
    int k = 2 * k2;
    const float* BG = net ? p_bg : g_bg;
    const float* BB = net ? p_bb : g_bb;
    const float* BM = net ? p_bm : g_bm;
    const float* BV = net ? p_bv : g_bv;
    float sc0 = BG[k] * rsqrtf(BV[k] + 1e-5f);
    float sh0 = BB[k] - BM[k] * sc0;
    float sc1 = BG[k + 1] * rsqrtf(BV[k + 1] + 1e-5f);
    float sh1 = BB[k + 1] - BM[k + 1] * sc1;
    const float* src = d_X + ((size_t)b * 1024 + net * 512 + k) * NEDGE + n;
    float v0 = fmaxf(src[0] * sc0 + sh0, 0.f);
    float v1 = fmaxf(src[NEDGE] * sc1 + sh1, 0.f);
    split_pair(v0, v1, d_Xph[idx], d_Xpl[idx]);
}

// ---------------- HMMA GEMM, cp.async double-buffered ----------------
// C[128x128] = A[128 x 2*K2TOT] @ B; operands pre-packed bf16 hi/lo k-pair u32.
// MODE 0 (intro):  X = D + Gi + Gj   (B indexed by b, K2TOT=768)
// MODE 1 (chorus): Y = D + X + cb    (B indexed by z=b*2+net, K2TOT=256)
template<int K2TOT, int MODE>
__global__ void __launch_bounds__(256, 2) gemm_mma(
    const uint32_t* __restrict__ Ah_g, const uint32_t* __restrict__ Al_g,
    const uint32_t* __restrict__ Bh_g, const uint32_t* __restrict__ Bl_g,
    const float* __restrict__ g_cb, const float* __restrict__ p_cb)
{
    extern __shared__ uint32_t smw[];
    const uint32_t sbase = smem_u32(smw);

    const int tid  = threadIdx.x;
    const int lane = tid & 31, wid = tid >> 5;
    const int wm = wid >> 2, wn = wid & 3;
    const int b    = blockIdx.z;
    const int row0 = blockIdx.y * 128;
    const int col0 = blockIdx.x * 128;
    const int net  = row0 >> 9;
    const int rbase = row0 & 511;

    const uint32_t* Ah = Ah_g + (size_t)(net * 512 + rbase) * K2TOT;
    const uint32_t* Al = Al_g + (size_t)(net * 512 + rbase) * K2TOT;
    const int bz = (MODE == 0) ? b : (b * 2 + net);
    const uint32_t* Bh = Bh_g + (size_t)bz * K2TOT * 1024 + col0;
    const uint32_t* Bl = Bl_g + (size_t)bz * K2TOT * 1024 + col0;

    constexpr int NCH = K2TOT / 16;

    // prefetch macro: 8 cp.async (16B) per thread per chunk + commit
    #define PREFETCH(kc, bufw) do { \
        _Pragma("unroll") \
        for (int i = 0; i < 2; i++) { \
            int t = tid + i * 256; \
            int row = t >> 2, seg = t & 3; \
            size_t go = (size_t)row * K2TOT + (kc) * 16 + seg * 4; \
            cpa16(sbase + ((bufw) + AH_O + row * 20 + seg * 4) * 4, Ah + go); \
            cpa16(sbase + ((bufw) + AL_O + row * 20 + seg * 4) * 4, Al + go); \
            int brow = t >> 5, bseg = t & 31; \
            size_t gb = (size_t)((kc) * 16 + brow) * 1024 + bseg * 4; \
            cpa16(sbase + ((bufw) + BH_O + brow * 136 + bseg * 4) * 4, Bh + gb); \
            cpa16(sbase + ((bufw) + BL_O + brow * 136 + bseg * 4) * 4, Bl + gb); \
        } \
        asm volatile("cp.async.commit_group;" ::: "memory"); \
    } while (0)

    float acc[4][4][4];
    #pragma unroll
    for (int i = 0; i < 4; i++)
        #pragma unroll
        for (int j = 0; j < 4; j++)
            #pragma unroll
            for (int v = 0; v < 4; v++) acc[i][j][v] = 0.f;

    PREFETCH(0, 0);

    #pragma unroll 1
    for (int kc = 0; kc < NCH; kc++) {
        const int bufw = (kc & 1) * BUF_WORDS;
        if (kc + 1 < NCH) {
            PREFETCH(kc + 1, ((kc + 1) & 1) * BUF_WORDS);
            asm volatile("cp.async.wait_group 1;" ::: "memory");
        } else {
            asm volatile("cp.async.wait_group 0;" ::: "memory");
        }
        __syncthreads();

        const uint32_t* AhS = smw + bufw + AH_O;
        const uint32_t* AlS = smw + bufw + AL_O;
        const uint32_t* BhS = smw + bufw + BH_O;
        const uint32_t* BlS = smw + bufw + BL_O;

        #pragma unroll
        for (int s = 0; s < 2; s++) {
            const int k2a = s * 8 + (lane & 3);
            uint32_t bh[4][2], bl[4][2];
            #pragma unroll
            for (int nf = 0; nf < 4; nf++) {
                int n = wn * 32 + nf * 8 + (lane >> 2);
                bh[nf][0] = BhS[k2a * 136 + n];
                bh[nf][1] = BhS[(k2a + 4) * 136 + n];
                bl[nf][0] = BlS[k2a * 136 + n];
                bl[nf][1] = BlS[(k2a + 4) * 136 + n];
            }
            #pragma unroll
            for (int mf = 0; mf < 4; mf++) {
                int row = wm * 64 + mf * 16 + (lane >> 2);
                uint32_t ah[4], al[4];
                ah[0] = AhS[row * 20 + k2a];       ah[1] = AhS[(row + 8) * 20 + k2a];
                ah[2] = AhS[row * 20 + k2a + 4];   ah[3] = AhS[(row + 8) * 20 + k2a + 4];
                al[0] = AlS[row * 20 + k2a];       al[1] = AlS[(row + 8) * 20 + k2a];
                al[2] = AlS[row * 20 + k2a + 4];   al[3] = AlS[(row + 8) * 20 + k2a + 4];
                #pragma unroll
                for (int nf = 0; nf < 4; nf++) {
                    mma16816(acc[mf][nf], ah, bh[nf]);
                    mma16816(acc[mf][nf], ah, bl[nf]);
                    mma16816(acc[mf][nf], al, bh[nf]);
                }
            }
        }
        __syncthreads();
    }
    #undef PREFETCH

    // ---- epilogue ----
    #pragma unroll
    for (int mf = 0; mf < 4; mf++) {
        int row_g = row0 + wm * 64 + mf * 16 + (lane >> 2);
        size_t obase = ((size_t)b * 1024 + row_g) * NEDGE;
        #pragma unroll
        for (int nf = 0; nf < 4; nf++) {
            int colg = col0 + wn * 32 + nf * 8 + (lane & 3) * 2;
            float* a = acc[mf][nf];
            if (MODE == 0) {
                int gir = b * 2048 + row_g + net * 512;
                int gjr = gir + 512;
                int ii = colg >> 5, jj = colg & 31;
                float Gi0 = d_Gn[(size_t)gir * NPT + ii];
                float Gi8 = d_Gn[(size_t)(gir + 8) * NPT + ii];
                float2 w0 = make_float2(a[0] + Gi0 + d_Gn[(size_t)gjr * NPT + jj],
                                        a[1] + Gi0 + d_Gn[(size_t)gjr * NPT + jj + 1]);
                float2 w1 = make_float2(a[2] + Gi8 + d_Gn[(size_t)(gjr + 8) * NPT + jj],
                                        a[3] + Gi8 + d_Gn[(size_t)(gjr + 8) * NPT + jj + 1]);
                *(float2*)&d_X[obase + colg] = w0;
                *(float2*)&d_X[obase + 8 * NEDGE + colg] = w1;
            } else {
                int r = row_g & 511;
                const float* CB = net ? p_cb : g_cb;
                float cb0 = CB[r], cb8 = CB[r + 8];
                float2 x0 = *(const float2*)&d_X[obase + colg];
                float2 x1 = *(const float2*)&d_X[obase + 8 * NEDGE + colg];
                float2 w0 = make_float2(a[0] + x0.x + cb0, a[1] + x0.y + cb0);
                float2 w1 = make_float2(a[2] + x1.x + cb8, a[3] + x1.y + cb8);
                *(float2*)&d_Y[obase + colg] = w0;
                *(float2*)&d_Y[obase + 8 * NEDGE + colg] = w1;
            }
        }
    }
}

// ---------------- K5: outro ----------------
__global__ void outro_kernel(const float* __restrict__ g_ow, const float* __restrict__ g_ob,
                             const float* __restrict__ p_ow, const float* __restrict__ p_ob)
{
    const int m  = blockIdx.x * 64 + threadIdx.x;
    const int oc = blockIdx.y * 8 + threadIdx.y;
    const int b  = blockIdx.z;
    if (oc >= 65) return;

    const float* Yb = d_Y + (size_t)b * 1024 * NEDGE;
    const float* w;
    const float* ysrc;
    float acc;
    if (oc == 0) { w = g_ow;                          acc = g_ob[0];       ysrc = Yb; }
    else         { w = p_ow + (size_t)(oc - 1) * 512; acc = p_ob[oc - 1];  ysrc = Yb + (size_t)512 * NEDGE; }

    #pragma unroll 8
    for (int r = 0; r < 512; r++)
        acc += w[r] * ysrc[(size_t)r * NEDGE + m];

    if (oc == 0) d_gate[b * NEDGE + m] = acc;
    else         d_pr[((size_t)b * 64 + (oc - 1)) * NEDGE + m] = acc;
}

// ---------------- K6: final ----------------
__global__ void final_kernel(const int* __restrict__ nvec, float* __restrict__ out)
{
    const int m = blockIdx.x * blockDim.x + threadIdx.x;
    const int b = blockIdx.y;
    if (m >= NEDGE) return;
    const int i = m >> 5, j = m & 31;
    const int nb = nvec[b];
    const bool ok = (i < nb) && (j < nb);

    float pv[64];
    float ss = 0.f;
    #pragma unroll
    for (int c = 0; c < 64; c++) {
        pv[c] = d_pr[((size_t)b * 64 + c) * NEDGE + m];
        ss += pv[c] * pv[c];
    }
    float g = 1.f / (1.f + expf(-d_gate[b * NEDGE + m]));
    float s = ok ? (g / fmaxf(sqrtf(ss), 1e-12f)) : 0.f;

    #pragma unroll
    for (int c = 0; c < 64; c++)
        out[((size_t)b * 64 + c) * NEDGE + m] = pv[c] * s;
}

// ---------------- launch ----------------
extern "C" void kernel_launch(void* const* d_in, const int* in_sizes, int n_in,
                              void* d_out, int out_size)
{
    const float* f0 = (const float*)d_in[0];
    const float* f1 = (const float*)d_in[1];
    const float* f2 = (const float*)d_in[2];
    const float* f3 = (const float*)d_in[3];
    const float* f4 = (const float*)d_in[4];
    const float* f5 = (const float*)d_in[5];
    const float* P  = (const float*)d_in[6];
    const int*   nv = (const int*)d_in[7];
    const float* g_iw = (const float*)d_in[8];
    const float* g_ib = (const float*)d_in[9];
    const float* g_bg = (const float*)d_in[10];
    const float* g_bb = (const float*)d_in[11];
    const float* g_bm = (const float*)d_in[12];
    const float* g_bv = (const float*)d_in[13];
    const float* g_cw = (const float*)d_in[14];
    const float* g_cb = (const float*)d_in[15];
    const float* g_ow = (const float*)d_in[16];
    const float* g_ob = (const float*)d_in[17];
    const float* p_iw = (const float*)d_in[18];
    const float* p_ib = (const float*)d_in[19];
    const float* p_bg = (const float*)d_in[20];
    const float* p_bb = (const float*)d_in[21];
    const float* p_bm = (const float*)d_in[22];
    const float* p_bv = (const float*)d_in[23];
    const float* p_cw = (const float*)d_in[24];
    const float* p_cb = (const float*)d_in[25];
    const float* p_ow = (const float*)d_in[26];
    const float* p_ob = (const float*)d_in[27];
    float* out = (float*)d_out;

    cudaFuncSetAttribute(gemm_mma<768, 0>, cudaFuncAttributeMaxDynamicSharedMemorySize, GEMM_SMEM_BYTES);
    cudaFuncSetAttribute(gemm_mma<256, 1>, cudaFuncAttributeMaxDynamicSharedMemorySize, GEMM_SMEM_BYTES);

    uint32_t *pWIh, *pWIl, *pCWh, *pCWl, *pEph, *pEpl, *pXph, *pXpl;
    cudaGetSymbolAddress((void**)&pWIh, d_WIh);
    cudaGetSymbolAddress((void**)&pWIl, d_WIl);
    cudaGetSymbolAddress((void**)&pCWh, d_CWh);
    cudaGetSymbolAddress((void**)&pCWl, d_CWl);
    cudaGetSymbolAddress((void**)&pEph, d_Eph);
    cudaGetSymbolAddress((void**)&pEpl, d_Epl);
    cudaGetSymbolAddress((void**)&pXph, d_Xph);
    cudaGetSymbolAddress((void**)&pXpl, d_Xpl);

    align_kernel<<<dim3(33, BSZ), dim3(32, 8)>>>(f0, f1, f2, f3, f4, f5, P);
    convWI<<<(2 * 512 * 768) / 256, 256>>>(g_iw, p_iw);
    convWC<<<(2 * 512 * 256) / 256, 256>>>(g_cw, p_cw);
    node_gemm<<<dim3(256, BSZ), dim3(32, 8)>>>(g_iw, p_iw, g_ib, p_ib);
    convE<<<(BSZ * 768 * 1024) / 256, 256>>>();

    gemm_mma<768, 0><<<dim3(8, 8, BSZ), 256, GEMM_SMEM_BYTES>>>(
        pWIh, pWIl, pEph, pEpl, nullptr, nullptr);

    convX<<<(BSZ * 2 * 256 * 1024) / 256, 256>>>(g_bg, g_bb, g_bm, g_bv,
                                                 p_bg, p_bb, p_bm, p_bv);

    gemm_mma<256, 1><<<dim3(8, 8, BSZ), 256, GEMM_SMEM_BYTES>>>(
        pCWh, pCWl, pXph, pXpl, g_cb, p_cb);

    outro_kernel<<<dim3(16, 9, BSZ), dim3(64, 8)>>>(g_ow, g_ob, p_ow, p_ob);
    final_kernel<<<dim3(4, BSZ), 256>>>(nv, out);
}

// round 8
// speedup vs baseline: 2.3794x; 1.3813x over previous
#include <cuda_runtime.h>
#include <cuda_bf16.h>
#include <math.h>
#include <stdint.h>

// ---------------- problem constants ----------------
#define BSZ   8
#define NPT   32
#define NEDGE 1024
#define NPTS  1056
#define LATC  1536

// ---------------- gemm smem layout (u32 words) ----------------
#define A_WORDS (128 * 20)
#define B_WORDS (16 * 136)
#define BUF_WORDS (2 * A_WORDS + 2 * B_WORDS)     // Ah, Al, Bh, Bl
#define AH_O 0
#define AL_O A_WORDS
#define BH_O (2 * A_WORDS)
#define BL_O (2 * A_WORDS + B_WORDS)
#define GEMM_SMEM_BYTES (2 * BUF_WORDS * 4)       // 75776 B

// ---------------- scratch (__device__ globals) ----------------
__device__ float d_A [BSZ * LATC * NPTS];   // aligned features [b][c][pid]
__device__ float d_Gn[BSZ * 2048 * NPT];    // node GEMM rows [g_i, g_j, p_i, p_j]
__device__ float d_GnP[4 * BSZ * 2048 * NPT]; // node GEMM k-split partials
__device__ float d_X [BSZ * 1024 * NEDGE];  // intro output
__device__ float d_Y [BSZ * 1024 * NEDGE];  // chorus output
__device__ float d_gateP[4 * BSZ * NEDGE];         // outro k-split partials
__device__ float d_prP [4 * BSZ * 64 * NEDGE];

// packed bf16 k-pair operands (u32 = (bf16 k, bf16 k+1)); hi / lo split
__device__ __align__(16) uint32_t d_WIh[2 * 512 * 768];   // intro E-weights [net*512+r][k2]
__device__ __align__(16) uint32_t d_WIl[2 * 512 * 768];
__device__ __align__(16) uint32_t d_CWh[2 * 512 * 256];   // chorus weights
__device__ __align__(16) uint32_t d_CWl[2 * 512 * 256];
__device__ __align__(16) uint32_t d_WNh[2048 * 768];      // node weights [g_i,g_j,p_i,p_j]
__device__ __align__(16) uint32_t d_WNl[2048 * 768];
__device__ __align__(16) uint32_t d_Eph[BSZ * 768 * 1024];  // E [b][k2][n]
__device__ __align__(16) uint32_t d_Epl[BSZ * 768 * 1024];
__device__ __align__(16) uint32_t d_Fnh[768 * 256];       // node F [k2][b*32+p]
__device__ __align__(16) uint32_t d_Fnl[768 * 256];
__device__ __align__(16) uint32_t d_Xph[BSZ * 2 * 256 * 1024]; // relu(BN(X)) [z][k2][n]
__device__ __align__(16) uint32_t d_Xpl[BSZ * 2 * 256 * 1024];

// ---------------- helpers ----------------
__device__ __forceinline__ void split_pair(float x, float y, uint32_t& hp, uint32_t& lp) {
    __nv_bfloat16 hx = __float2bfloat16_rn(x), hy = __float2bfloat16_rn(y);
    __nv_bfloat16 lx = __float2bfloat16_rn(x - __bfloat162float(hx));
    __nv_bfloat16 ly = __float2bfloat16_rn(y - __bfloat162float(hy));
    __nv_bfloat162 h2(hx, hy), l2(lx, ly);
    hp = *reinterpret_cast<uint32_t*>(&h2);
    lp = *reinterpret_cast<uint32_t*>(&l2);
}

__device__ __forceinline__ void mma16816(float* c, const uint32_t* a, const uint32_t* b) {
    asm volatile("mma.sync.aligned.m16n8k16.row.col.f32.bf16.bf16.f32 "
                 "{%0,%1,%2,%3}, {%4,%5,%6,%7}, {%8,%9}, {%0,%1,%2,%3};"
                 : "+f"(c[0]), "+f"(c[1]), "+f"(c[2]), "+f"(c[3])
                 : "r"(a[0]), "r"(a[1]), "r"(a[2]), "r"(a[3]),
                   "r"(b[0]), "r"(b[1]));
}

__device__ __forceinline__ uint32_t smem_u32(const void* p) {
    uint32_t a;
    asm("{ .reg .u64 t; cvta.to.shared.u64 t, %1; cvt.u32.u64 %0, t; }" : "=r"(a) : "l"(p));
    return a;
}
__device__ __forceinline__ void cpa16(uint32_t dst_s, const void* src) {
    asm volatile("cp.async.cg.shared.global [%0], [%1], 16;" :: "r"(dst_s), "l"(src));
}

// ---------------- K1: bilinear align at all 1056 points ----------------
__global__ void align_kernel(const float* __restrict__ f0, const float* __restrict__ f1,
                             const float* __restrict__ f2, const float* __restrict__ f3,
                             const float* __restrict__ f4, const float* __restrict__ f5,
                             const float* __restrict__ P)
{
    const int pid = blockIdx.x * 32 + threadIdx.x;
    const int b   = blockIdx.y;
    if (pid >= NPTS) return;

    float px, py;
    if (pid < NPT) {
        px = P[(b * NPT + pid) * 2 + 0];
        py = P[(b * NPT + pid) * 2 + 1];
    } else {
        int m = pid - NPT;
        int i = m >> 5, j = m & 31;
        px = 0.5f * (P[(b * NPT + i) * 2 + 0] + P[(b * NPT + j) * 2 + 0]);
        py = 0.5f * (P[(b * NPT + i) * 2 + 1] + P[(b * NPT + j) * 2 + 1]);
    }

    const float* feats[6] = { f0, f1, f2, f3, f4, f5 };
    const int Cs[6] = { 64, 64, 128, 256, 512, 512 };
    const int Hs[6] = { 128, 64, 32, 16, 8, 1 };

    int choff = 0;
    #pragma unroll
    for (int l = 0; l < 6; l++) {
        const int C = Cs[l], H = Hs[l];
        float xs = fminf(fmaxf(px * ((float)H * (1.0f / 256.0f)) - 0.5f, 0.0f), (float)(H - 1));
        float ys = fminf(fmaxf(py * ((float)H * (1.0f / 256.0f)) - 0.5f, 0.0f), (float)(H - 1));
        float x0f = floorf(xs), y0f = floorf(ys);
        float wx = xs - x0f, wy = ys - y0f;
        int x0 = (int)x0f, y0 = (int)y0f;
        int x1 = min(x0 + 1, H - 1), y1 = min(y0 + 1, H - 1);
        float w00 = (1.f - wx) * (1.f - wy);
        float w01 = wx * (1.f - wy);
        float w10 = (1.f - wx) * wy;
        float w11 = wx * wy;
        int i00 = y0 * H + x0, i01 = y0 * H + x1, i10 = y1 * H + x0, i11 = y1 * H + x1;
        const float* f = feats[l];
        const int hw = H * H;
        for (int c = threadIdx.y; c < C; c += 8) {
            const float* base = f + (size_t)(b * C + c) * hw;
            float v = base[i00] * w00 + base[i01] * w01 + base[i10] * w10 + base[i11] * w11;
            d_A[((size_t)b * LATC + choff + c) * NPTS + pid] = v;
        }
        choff += C;
    }
}

// ---------------- conversion kernels ----------------
__global__ void convWI(const float* __restrict__ g_iw, const float* __restrict__ p_iw)
{
    int idx = blockIdx.x * 256 + threadIdx.x;       // 2*512*768
    int k2 = idx % 768;
    int r  = (idx / 768) & 511;
    int net = idx / (512 * 768);
    const float* w = (net ? p_iw : g_iw) + (size_t)r * 4608 + 3072 + 2 * k2;
    split_pair(w[0], w[1], d_WIh[idx], d_WIl[idx]);
}

__global__ void convWC(const float* __restrict__ g_cw, const float* __restrict__ p_cw)
{
    int idx = blockIdx.x * 256 + threadIdx.x;       // 2*512*256
    int k2 = idx & 255;
    int r  = (idx >> 8) & 511;
    int net = idx >> 17;
    const float* w = (net ? p_cw : g_cw) + (size_t)r * 512 + 2 * k2;
    split_pair(w[0], w[1], d_CWh[idx], d_CWl[idx]);
}

// node weights: rows [0,512)=g_i, [512,1024)=g_j, [1024,1536)=p_i, [1536,2048)=p_j
__global__ void convWN(const float* __restrict__ g_iw, const float* __restrict__ p_iw)
{
    int idx = blockIdx.x * 256 + threadIdx.x;       // 2048*768
    int k2 = idx % 768;
    int r  = idx / 768;
    int part = r >> 9;
    const float* w = (part >= 2 ? p_iw : g_iw) + (size_t)(r & 511) * 4608
                     + ((part & 1) ? 1536 : 0) + 2 * k2;
    split_pair(w[0], w[1], d_WNh[idx], d_WNl[idx]);
}

__global__ void convE()
{
    int idx = blockIdx.x * 256 + threadIdx.x;       // 8*768*1024
    int n  = idx & 1023;
    int t  = idx >> 10;
    int k2 = t % 768;
    int b  = t / 768;
    const float* src = d_A + ((size_t)b * LATC + 2 * k2) * NPTS + NPT + n;
    split_pair(src[0], src[NPTS], d_Eph[idx], d_Epl[idx]);
}

// node F: [k2][n] with n = b*32 + p (node points)
__global__ void convF()
{
    int idx = blockIdx.x * 256 + threadIdx.x;       // 768*256
    int n  = idx & 255;
    int k2 = idx >> 8;
    int b = n >> 5, p = n & 31;
    const float* src = d_A + ((size_t)b * LATC + 2 * k2) * NPTS + p;
    split_pair(src[0], src[NPTS], d_Fnh[idx], d_Fnl[idx]);
}

__global__ void convX(const float* __restrict__ g_bg, const float* __restrict__ g_bb,
                      const float* __restrict__ g_bm, const float* __restrict__ g_bv,
                      const float* __restrict__ p_bg, const float* __restrict__ p_bb,
                      const float* __restrict__ p_bm, const float* __restrict__ p_bv)
{
    int idx = blockIdx.x * 256 + threadIdx.x;       // 8*2*256*1024
    int n  = idx & 1023;
    int t  = idx >> 10;
    int k2 = t & 255;
    int z  = t >> 8;
    int b = z >> 1, net = z & 1;
    int k = 2 * k2;
    const float* BG = net ? p_bg : g_bg;
    const float* BB = net ? p_bb : g_bb;
    const float* BM = net ? p_bm : g_bm;
    const float* BV = net ? p_bv : g_bv;
    float sc0 = BG[k] * rsqrtf(BV[k] + 1e-5f);
    float sh0 = BB[k] - BM[k] * sc0;
    float sc1 = BG[k + 1] * rsqrtf(BV[k + 1] + 1e-5f);
    float sh1 = BB[k + 1] - BM[k + 1] * sc1;
    const float* src = d_X + ((size_t)b * 1024 + net * 512 + k) * NEDGE + n;
    float v0 = fmaxf(src[0] * sc0 + sh0, 0.f);
    float v1 = fmaxf(src[NEDGE] * sc1 + sh1, 0.f);
    split_pair(v0, v1, d_Xph[idx], d_Xpl[idx]);
}

// ---------------- HMMA GEMM, cp.async double-buffered ----------------
// C[128x128] = A[128 x 2*K2TOT] @ B; operands pre-packed bf16 hi/lo k-pair u32.
// MODE 0 (intro):  X = D + Gi + Gj        (B indexed by b=blockIdx.z, NTOT=1024)
// MODE 1 (chorus): Y = D + X + cb         (B indexed by z=b*2+net, NTOT=1024)
// MODE 2 (node):   GnP[z] = D partials    (NTOT=256, blockIdx.z = k-split)
template<int K2TOT, int NTOT, int MODE>
__global__ void __launch_bounds__(256, 2) gemm_mma(
    const uint32_t* __restrict__ Ah_g, const uint32_t* __restrict__ Al_g,
    const uint32_t* __restrict__ Bh_g, const uint32_t* __restrict__ Bl_g,
    const float* __restrict__ g_cb, const float* __restrict__ p_cb)
{
    extern __shared__ uint32_t smw[];
    const uint32_t sbase = smem_u32(smw);

    const int tid  = threadIdx.x;
    const int lane = tid & 31, wid = tid >> 5;
    const int wm = wid >> 2, wn = wid & 3;
    const int b    = blockIdx.z;
    const int row0 = blockIdx.y * 128;
    const int col0 = blockIdx.x * 128;
    const int net  = (row0 >> 9) & 1;

    const uint32_t* Ah = Ah_g + (size_t)row0 * K2TOT;
    const uint32_t* Al = Al_g + (size_t)row0 * K2TOT;
    const int bz = (MODE == 0) ? b : (MODE == 1 ? b * 2 + net : 0);
    const uint32_t* Bh = Bh_g + (size_t)bz * K2TOT * NTOT + col0;
    const uint32_t* Bl = Bl_g + (size_t)bz * K2TOT * NTOT + col0;

    constexpr int NCH = K2TOT / 16;
    constexpr int CHUNKS = (MODE == 2) ? NCH / 4 : NCH;
    const int kc0 = (MODE == 2) ? blockIdx.z * CHUNKS : 0;

    #define PREFETCH(kc, bufw) do { \
        _Pragma("unroll") \
        for (int i = 0; i < 2; i++) { \
            int t = tid + i * 256; \
            int row = t >> 2, seg = t & 3; \
            size_t go = (size_t)row * K2TOT + (kc) * 16 + seg * 4; \
            cpa16(sbase + ((bufw) + AH_O + row * 20 + seg * 4) * 4, Ah + go); \
            cpa16(sbase + ((bufw) + AL_O + row * 20 + seg * 4) * 4, Al + go); \
            int brow = t >> 5, bseg = t & 31; \
            size_t gb = (size_t)((kc) * 16 + brow) * NTOT + bseg * 4; \
            cpa16(sbase + ((bufw) + BH_O + brow * 136 + bseg * 4) * 4, Bh + gb); \
            cpa16(sbase + ((bufw) + BL_O + brow * 136 + bseg * 4) * 4, Bl + gb); \
        } \
        asm volatile("cp.async.commit_group;" ::: "memory"); \
    } while (0)

    float acc[4][4][4];
    #pragma unroll
    for (int i = 0; i < 4; i++)
        #pragma unroll
        for (int j = 0; j < 4; j++)
            #pragma unroll
            for (int v = 0; v < 4; v++) acc[i][j][v] = 0.f;

    PREFETCH(kc0, 0);

    #pragma unroll 1
    for (int ci = 0; ci < CHUNKS; ci++) {
        const int bufw = (ci & 1) * BUF_WORDS;
        if (ci + 1 < CHUNKS) {
            PREFETCH(kc0 + ci + 1, ((ci + 1) & 1) * BUF_WORDS);
            asm volatile("cp.async.wait_group 1;" ::: "memory");
        } else {
            asm volatile("cp.async.wait_group 0;" ::: "memory");
        }
        __syncthreads();

        const uint32_t* AhS = smw + bufw + AH_O;
        const uint32_t* AlS = smw + bufw + AL_O;
        const uint32_t* BhS = smw + bufw + BH_O;
        const uint32_t* BlS = smw + bufw + BL_O;

        #pragma unroll
        for (int s = 0; s < 2; s++) {
            const int k2a = s * 8 + (lane & 3);
            uint32_t bh[4][2], bl[4][2];
            #pragma unroll
            for (int nf = 0; nf < 4; nf++) {
                int n = wn * 32 + nf * 8 + (lane >> 2);
                bh[nf][0] = BhS[k2a * 136 + n];
                bh[nf][1] = BhS[(k2a + 4) * 136 + n];
                bl[nf][0] = BlS[k2a * 136 + n];
                bl[nf][1] = BlS[(k2a + 4) * 136 + n];
            }
            #pragma unroll
            for (int mf = 0; mf < 4; mf++) {
                int row = wm * 64 + mf * 16 + (lane >> 2);
                uint32_t ah[4], al[4];
                ah[0] = AhS[row * 20 + k2a];       ah[1] = AhS[(row + 8) * 20 + k2a];
                ah[2] = AhS[row * 20 + k2a + 4];   ah[3] = AhS[(row + 8) * 20 + k2a + 4];
                al[0] = AlS[row * 20 + k2a];       al[1] = AlS[(row + 8) * 20 + k2a];
                al[2] = AlS[row * 20 + k2a + 4];   al[3] = AlS[(row + 8) * 20 + k2a + 4];
                #pragma unroll
                for (int nf = 0; nf < 4; nf++) {
                    mma16816(acc[mf][nf], ah, bh[nf]);
                    mma16816(acc[mf][nf], ah, bl[nf]);
                    mma16816(acc[mf][nf], al, bh[nf]);
                }
            }
        }
        __syncthreads();
    }
    #undef PREFETCH

    // ---- epilogue ----
    #pragma unroll
    for (int mf = 0; mf < 4; mf++) {
        int row_g = row0 + wm * 64 + mf * 16 + (lane >> 2);
        #pragma unroll
        for (int nf = 0; nf < 4; nf++) {
            int colg = col0 + wn * 32 + nf * 8 + (lane & 3) * 2;
            float* a = acc[mf][nf];
            if (MODE == 2) {
                int bb = colg >> 5, p = colg & 31;
                float* dst = d_GnP + (((size_t)blockIdx.z * 8 + bb) * 2048) * NPT;
                *(float2*)&dst[(size_t)row_g * NPT + p] = make_float2(a[0], a[1]);
                *(float2*)&dst[(size_t)(row_g + 8) * NPT + p] = make_float2(a[2], a[3]);
            } else if (MODE == 0) {
                size_t obase = ((size_t)b * 1024 + row_g) * NEDGE;
                int gir = b * 2048 + row_g + net * 512;
                int gjr = gir + 512;
                int ii = colg >> 5, jj = colg & 31;
                float Gi0 = d_Gn[(size_t)gir * NPT + ii];
                float Gi8 = d_Gn[(size_t)(gir + 8) * NPT + ii];
                float2 w0 = make_float2(a[0] + Gi0 + d_Gn[(size_t)gjr * NPT + jj],
                                        a[1] + Gi0 + d_Gn[(size_t)gjr * NPT + jj + 1]);
                float2 w1 = make_float2(a[2] + Gi8 + d_Gn[(size_t)(gjr + 8) * NPT + jj],
                                        a[3] + Gi8 + d_Gn[(size_t)(gjr + 8) * NPT + jj + 1]);
                *(float2*)&d_X[obase + colg] = w0;
                *(float2*)&d_X[obase + 8 * NEDGE + colg] = w1;
            } else {
                size_t obase = ((size_t)b * 1024 + row_g) * NEDGE;
                int r = row_g & 511;
                const float* CB = net ? p_cb : g_cb;
                float cb0 = CB[r], cb8 = CB[r + 8];
                float2 x0 = *(const float2*)&d_X[obase + colg];
                float2 x1 = *(const float2*)&d_X[obase + 8 * NEDGE + colg];
                float2 w0 = make_float2(a[0] + x0.x + cb0, a[1] + x0.y + cb0);
                float2 w1 = make_float2(a[2] + x1.x + cb8, a[3] + x1.y + cb8);
                *(float2*)&d_Y[obase + colg] = w0;
                *(float2*)&d_Y[obase + 8 * NEDGE + colg] = w1;
            }
        }
    }
}

// ---------------- reduce node partials + bias ----------------
__global__ void reduceGn(const float* __restrict__ g_ib, const float* __restrict__ p_ib)
{
    int idx = blockIdx.x * 256 + threadIdx.x;   // 8*2048*32
    int r = (idx >> 5) & 2047;
    float bias = (r < 512) ? g_ib[r] : ((r >= 1024 && r < 1536) ? p_ib[r - 1024] : 0.f);
    float s = bias;
    #pragma unroll
    for (int z = 0; z < 4; z++)
        s += d_GnP[(size_t)z * (8 * 2048 * NPT) + idx];
    d_Gn[idx] = s;
}

// ---------------- K5: outro (Y streamed once, all 65 oc in regs) ----------------
__global__ void __launch_bounds__(128) outro_kernel(const float* __restrict__ g_ow,
                                                    const float* __restrict__ p_ow)
{
    __shared__ float wg[128];
    __shared__ float wp[64 * 128];
    const int tx = threadIdx.x;
    const int m  = blockIdx.x * 128 + tx;
    const int b  = blockIdx.y;
    const int rz = blockIdx.z;       // k-split 0..3
    const int r0 = rz * 128;

    wg[tx] = g_ow[r0 + tx];
    for (int i = tx; i < 64 * 128; i += 128) {
        int oc = i >> 7, r = i & 127;
        wp[i] = p_ow[(size_t)oc * 512 + r0 + r];
    }
    __syncthreads();

    float accg = 0.f;
    float acc[64];
    #pragma unroll
    for (int oc = 0; oc < 64; oc++) acc[oc] = 0.f;

    const float* Yg = d_Y + ((size_t)b * 1024 + r0) * NEDGE + m;
    const float* Yp = Yg + (size_t)512 * NEDGE;
    #pragma unroll 4
    for (int r = 0; r < 128; r++) {
        float yg = Yg[(size_t)r * NEDGE];
        float yp = Yp[(size_t)r * NEDGE];
        accg += wg[r] * yg;
        #pragma unroll
        for (int oc = 0; oc < 64; oc++)
            acc[oc] += wp[oc * 128 + r] * yp;
    }

    d_gateP[((size_t)rz * 8 + b) * NEDGE + m] = accg;
    float* dst = d_prP + ((size_t)rz * 8 + b) * 64 * NEDGE + m;
    #pragma unroll
    for (int oc = 0; oc < 64; oc++)
        dst[(size_t)oc * NEDGE] = acc[oc];
}

// ---------------- K6: final (reduce partials, sigmoid*normalize*mask) ----------------
__global__ void final_kernel(const int* __restrict__ nvec,
                             const float* __restrict__ g_ob, const float* __restrict__ p_ob,
                             float* __restrict__ out)
{
    const int m = blockIdx.x * blockDim.x + threadIdx.x;
    const int b = blockIdx.y;
    if (m >= NEDGE) return;
    const int i = m >> 5, j = m & 31;
    const int nb = nvec[b];
    const bool ok = (i < nb) && (j < nb);

    float gsum = g_ob[0];
    #pragma unroll
    for (int z = 0; z < 4; z++)
        gsum += d_gateP[((size_t)z * 8 + b) * NEDGE + m];

    float pv[64];
    float ss = 0.f;
    #pragma unroll
    for (int c = 0; c < 64; c++) {
        float v = p_ob[c];
        #pragma unroll
        for (int z = 0; z < 4; z++)
            v += d_prP[(((size_t)z * 8 + b) * 64 + c) * NEDGE + m];
        pv[c] = v;
        ss += v * v;
    }
    float g = 1.f / (1.f + expf(-gsum));
    float s = ok ? (g / fmaxf(sqrtf(ss), 1e-12f)) : 0.f;

    #pragma unroll
    for (int c = 0; c < 64; c++)
        out[((size_t)b * 64 + c) * NEDGE + m] = pv[c] * s;
}

// ---------------- launch ----------------
extern "C" void kernel_launch(void* const* d_in, const int* in_sizes, int n_in,
                              void* d_out, int out_size)
{
    const float* f0 = (const float*)d_in[0];
    const float* f1 = (const float*)d_in[1];
    const float* f2 = (const float*)d_in[2];
    const float* f3 = (const float*)d_in[3];
    const float* f4 = (const float*)d_in[4];
    const float* f5 = (const float*)d_in[5];
    const float* P  = (const float*)d_in[6];
    const int*   nv = (const int*)d_in[7];
    const float* g_iw = (const float*)d_in[8];
    const float* g_ib = (const float*)d_in[9];
    const float* g_bg = (const float*)d_in[10];
    const float* g_bb = (const float*)d_in[11];
    const float* g_bm = (const float*)d_in[12];
    const float* g_bv = (const float*)d_in[13];
    const float* g_cw = (const float*)d_in[14];
    const float* g_cb = (const float*)d_in[15];
    const float* g_ow = (const float*)d_in[16];
    const float* g_ob = (const float*)d_in[17];
    const float* p_iw = (const float*)d_in[18];
    const float* p_ib = (const float*)d_in[19];
    const float* p_bg = (const float*)d_in[20];
    const float* p_bb = (const float*)d_in[21];
    const float* p_bm = (const float*)d_in[22];
    const float* p_bv = (const float*)d_in[23];
    const float* p_cw = (const float*)d_in[24];
    const float* p_cb = (const float*)d_in[25];
    const float* p_ow = (const float*)d_in[26];
    const float* p_ob = (const float*)d_in[27];
    float* out = (float*)d_out;

    cudaFuncSetAttribute(gemm_mma<768, 1024, 0>, cudaFuncAttributeMaxDynamicSharedMemorySize, GEMM_SMEM_BYTES);
    cudaFuncSetAttribute(gemm_mma<256, 1024, 1>, cudaFuncAttributeMaxDynamicSharedMemorySize, GEMM_SMEM_BYTES);
    cudaFuncSetAttribute(gemm_mma<768, 256, 2>,  cudaFuncAttributeMaxDynamicSharedMemorySize, GEMM_SMEM_BYTES);

    uint32_t *pWIh, *pWIl, *pCWh, *pCWl, *pWNh, *pWNl, *pEph, *pEpl, *pFnh, *pFnl, *pXph, *pXpl;
    cudaGetSymbolAddress((void**)&pWIh, d_WIh);
    cudaGetSymbolAddress((void**)&pWIl, d_WIl);
    cudaGetSymbolAddress((void**)&pCWh, d_CWh);
    cudaGetSymbolAddress((void**)&pCWl, d_CWl);
    cudaGetSymbolAddress((void**)&pWNh, d_WNh);
    cudaGetSymbolAddress((void**)&pWNl, d_WNl);
    cudaGetSymbolAddress((void**)&pEph, d_Eph);
    cudaGetSymbolAddress((void**)&pEpl, d_Epl);
    cudaGetSymbolAddress((void**)&pFnh, d_Fnh);
    cudaGetSymbolAddress((void**)&pFnl, d_Fnl);
    cudaGetSymbolAddress((void**)&pXph, d_Xph);
    cudaGetSymbolAddress((void**)&pXpl, d_Xpl);

    align_kernel<<<dim3(33, BSZ), dim3(32, 8)>>>(f0, f1, f2, f3, f4, f5, P);
    convWI<<<(2 * 512 * 768) / 256, 256>>>(g_iw, p_iw);
    convWC<<<(2 * 512 * 256) / 256, 256>>>(g_cw, p_cw);
    convWN<<<(2048 * 768) / 256, 256>>>(g_iw, p_iw);
    convF <<<(768 * 256) / 256, 256>>>();
    convE <<<(BSZ * 768 * 1024) / 256, 256>>>();

    // node GEMM (k-split 4, partials) + reduce
    gemm_mma<768, 256, 2><<<dim3(2, 16, 4), 256, GEMM_SMEM_BYTES>>>(
        pWNh, pWNl, pFnh, pFnl, nullptr, nullptr);
    reduceGn<<<(BSZ * 2048 * NPT) / 256, 256>>>(g_ib, p_ib);

    gemm_mma<768, 1024, 0><<<dim3(8, 8, BSZ), 256, GEMM_SMEM_BYTES>>>(
        pWIh, pWIl, pEph, pEpl, nullptr, nullptr);

    convX<<<(BSZ * 2 * 256 * 1024) / 256, 256>>>(g_bg, g_bb, g_bm, g_bv,
                                                 p_bg, p_bb, p_bm, p_bv);

    gemm_mma<256, 1024, 1><<<dim3(8, 8, BSZ), 256, GEMM_SMEM_BYTES>>>(
        pCWh, pCWl, pXph, pXpl, g_cb, p_cb);

    outro_kernel<<<dim3(8, BSZ, 4), 128>>>(g_ow, p_ow);
    final_kernel<<<dim3(4, BSZ), 256>>>(nv, g_ob, p_ob, out);
}

// round 9
// speedup vs baseline: 2.5586x; 1.0753x over previous
#include <cuda_runtime.h>
#include <cuda_bf16.h>
#include <math.h>
#include <stdint.h>

// ---------------- problem constants ----------------
#define BSZ   8
#define NPT   32
#define NEDGE 1024
#define NPAIR 528            // unique (i<=j) midpoint pairs
#define NECOL 640            // padded unique-E columns (5 x 128)
#define NPTS  560            // 32 nodes + 528 unique midpoints
#define LATC  1536

// ---------------- gemm smem layout (u32 words) ----------------
#define A_WORDS (128 * 20)
#define B_WORDS (16 * 136)
#define BUF_WORDS (2 * A_WORDS + 2 * B_WORDS)     // Ah, Al, Bh, Bl
#define AH_O 0
#define AL_O A_WORDS
#define BH_O (2 * A_WORDS)
#define BL_O (2 * A_WORDS + B_WORDS)
#define GEMM_SMEM_BYTES (2 * BUF_WORDS * 4)       // 75776 B

// ---------------- scratch (__device__ globals) ----------------
__device__ float d_A [BSZ * LATC * NPTS];   // aligned features [b][c][pid]
__device__ float d_Gn[BSZ * 2048 * NPT];    // node rows [g_i, g_j, p_i, p_j]
__device__ float d_GnP[4 * BSZ * 2048 * NPT];
__device__ float d_X [BSZ * 1024 * NEDGE];
__device__ float d_Y [BSZ * 1024 * NEDGE];
__device__ float d_gateP[4 * BSZ * NEDGE];
__device__ float d_prP [4 * BSZ * 64 * NEDGE];
__device__ int   d_pi[NPAIR];
__device__ int   d_pj[NPAIR];

// packed bf16 k-pair operands (u32 = (bf16 k, bf16 k+1)); hi / lo split
__device__ __align__(16) uint32_t d_WIh[2 * 512 * 768];
__device__ __align__(16) uint32_t d_WIl[2 * 512 * 768];
__device__ __align__(16) uint32_t d_CWh[2 * 512 * 256];
__device__ __align__(16) uint32_t d_CWl[2 * 512 * 256];
__device__ __align__(16) uint32_t d_WNh[2048 * 768];
__device__ __align__(16) uint32_t d_WNl[2048 * 768];
__device__ __align__(16) uint32_t d_Eph[BSZ * 768 * NECOL];  // E unique [b][k2][c]
__device__ __align__(16) uint32_t d_Epl[BSZ * 768 * NECOL];
__device__ __align__(16) uint32_t d_Fnh[768 * 256];          // node F [k2][b*32+p]
__device__ __align__(16) uint32_t d_Fnl[768 * 256];
__device__ __align__(16) uint32_t d_Xph[BSZ * 2 * 256 * 1024];
__device__ __align__(16) uint32_t d_Xpl[BSZ * 2 * 256 * 1024];

// ---------------- helpers ----------------
__device__ __forceinline__ void split_pair(float x, float y, uint32_t& hp, uint32_t& lp) {
    __nv_bfloat16 hx = __float2bfloat16_rn(x), hy = __float2bfloat16_rn(y);
    __nv_bfloat16 lx = __float2bfloat16_rn(x - __bfloat162float(hx));
    __nv_bfloat16 ly = __float2bfloat16_rn(y - __bfloat162float(hy));
    __nv_bfloat162 h2(hx, hy), l2(lx, ly);
    hp = *reinterpret_cast<uint32_t*>(&h2);
    lp = *reinterpret_cast<uint32_t*>(&l2);
}

__device__ __forceinline__ void mma16816(float* c, const uint32_t* a, const uint32_t* b) {
    asm volatile("mma.sync.aligned.m16n8k16.row.col.f32.bf16.bf16.f32 "
                 "{%0,%1,%2,%3}, {%4,%5,%6,%7}, {%8,%9}, {%0,%1,%2,%3};"
                 : "+f"(c[0]), "+f"(c[1]), "+f"(c[2]), "+f"(c[3])
                 : "r"(a[0]), "r"(a[1]), "r"(a[2]), "r"(a[3]),
                   "r"(b[0]), "r"(b[1]));
}

__device__ __forceinline__ uint32_t smem_u32(const void* p) {
    uint32_t a;
    asm("{ .reg .u64 t; cvta.to.shared.u64 t, %1; cvt.u32.u64 %0, t; }" : "=r"(a) : "l"(p));
    return a;
}
__device__ __forceinline__ void cpa16(uint32_t dst_s, const void* src) {
    asm volatile("cp.async.cg.shared.global [%0], [%1], 16;" :: "r"(dst_s), "l"(src));
}

// ---------------- K0: pair index tables ----------------
__global__ void init_pairs()
{
    int c = blockIdx.x * 64 + threadIdx.x;
    if (c >= NPAIR) return;
    // row i has 32-i entries, base(i) = 32i - i(i-1)/2
    int i = 0, base = 0;
    while (base + (32 - i) <= c) { base += 32 - i; i++; }
    d_pi[c] = i;
    d_pj[c] = i + (c - base);
}

// ---------------- K1: bilinear align at 560 unique points ----------------
__global__ void align_kernel(const float* __restrict__ f0, const float* __restrict__ f1,
                             const float* __restrict__ f2, const float* __restrict__ f3,
                             const float* __restrict__ f4, const float* __restrict__ f5,
                             const float* __restrict__ P)
{
    const int pid = blockIdx.x * 32 + threadIdx.x;
    const int b   = blockIdx.y;
    if (pid >= NPTS) return;

    float px, py;
    if (pid < NPT) {
        px = P[(b * NPT + pid) * 2 + 0];
        py = P[(b * NPT + pid) * 2 + 1];
    } else {
        int pc = pid - NPT;
        int i = d_pi[pc], j = d_pj[pc];
        px = 0.5f * (P[(b * NPT + i) * 2 + 0] + P[(b * NPT + j) * 2 + 0]);
        py = 0.5f * (P[(b * NPT + i) * 2 + 1] + P[(b * NPT + j) * 2 + 1]);
    }

    const float* feats[6] = { f0, f1, f2, f3, f4, f5 };
    const int Cs[6] = { 64, 64, 128, 256, 512, 512 };
    const int Hs[6] = { 128, 64, 32, 16, 8, 1 };

    int choff = 0;
    #pragma unroll
    for (int l = 0; l < 6; l++) {
        const int C = Cs[l], H = Hs[l];
        float xs = fminf(fmaxf(px * ((float)H * (1.0f / 256.0f)) - 0.5f, 0.0f), (float)(H - 1));
        float ys = fminf(fmaxf(py * ((float)H * (1.0f / 256.0f)) - 0.5f, 0.0f), (float)(H - 1));
        float x0f = floorf(xs), y0f = floorf(ys);
        float wx = xs - x0f, wy = ys - y0f;
        int x0 = (int)x0f, y0 = (int)y0f;
        int x1 = min(x0 + 1, H - 1), y1 = min(y0 + 1, H - 1);
        float w00 = (1.f - wx) * (1.f - wy);
        float w01 = wx * (1.f - wy);
        float w10 = (1.f - wx) * wy;
        float w11 = wx * wy;
        int i00 = y0 * H + x0, i01 = y0 * H + x1, i10 = y1 * H + x0, i11 = y1 * H + x1;
        const float* f = feats[l];
        const int hw = H * H;
        for (int c = threadIdx.y; c < C; c += 8) {
            const float* base = f + (size_t)(b * C + c) * hw;
            float v = base[i00] * w00 + base[i01] * w01 + base[i10] * w10 + base[i11] * w11;
            d_A[((size_t)b * LATC + choff + c) * NPTS + pid] = v;
        }
        choff += C;
    }
}

// ---------------- conversion kernels ----------------
__global__ void convWI(const float* __restrict__ g_iw, const float* __restrict__ p_iw)
{
    int idx = blockIdx.x * 256 + threadIdx.x;       // 2*512*768
    int k2 = idx % 768;
    int r  = (idx / 768) & 511;
    int net = idx / (512 * 768);
    const float* w = (net ? p_iw : g_iw) + (size_t)r * 4608 + 3072 + 2 * k2;
    split_pair(w[0], w[1], d_WIh[idx], d_WIl[idx]);
}

__global__ void convWC(const float* __restrict__ g_cw, const float* __restrict__ p_cw)
{
    int idx = blockIdx.x * 256 + threadIdx.x;       // 2*512*256
    int k2 = idx & 255;
    int r  = (idx >> 8) & 511;
    int net = idx >> 17;
    const float* w = (net ? p_cw : g_cw) + (size_t)r * 512 + 2 * k2;
    split_pair(w[0], w[1], d_CWh[idx], d_CWl[idx]);
}

__global__ void convWN(const float* __restrict__ g_iw, const float* __restrict__ p_iw)
{
    int idx = blockIdx.x * 256 + threadIdx.x;       // 2048*768
    int k2 = idx % 768;
    int r  = idx / 768;
    int part = r >> 9;
    const float* w = (part >= 2 ? p_iw : g_iw) + (size_t)(r & 511) * 4608
                     + ((part & 1) ? 1536 : 0) + 2 * k2;
    split_pair(w[0], w[1], d_WNh[idx], d_WNl[idx]);
}

__global__ void convE()
{
    int idx = blockIdx.x * 256 + threadIdx.x;       // 8*768*640
    int n  = idx % NECOL;
    int t  = idx / NECOL;
    int k2 = t % 768;
    int b  = t / 768;
    if (n >= NPAIR) { d_Eph[idx] = 0u; d_Epl[idx] = 0u; return; }
    const float* src = d_A + ((size_t)b * LATC + 2 * k2) * NPTS + NPT + n;
    split_pair(src[0], src[NPTS], d_Eph[idx], d_Epl[idx]);
}

__global__ void convF()
{
    int idx = blockIdx.x * 256 + threadIdx.x;       // 768*256
    int n  = idx & 255;
    int k2 = idx >> 8;
    int b = n >> 5, p = n & 31;
    const float* src = d_A + ((size_t)b * LATC + 2 * k2) * NPTS + p;
    split_pair(src[0], src[NPTS], d_Fnh[idx], d_Fnl[idx]);
}

__global__ void convX(const float* __restrict__ g_bg, const float* __restrict__ g_bb,
                      const float* __restrict__ g_bm, const float* __restrict__ g_bv,
                      const float* __restrict__ p_bg, const float* __restrict__ p_bb,
                      const float* __restrict__ p_bm, const float* __restrict__ p_bv)
{
    int idx = blockIdx.x * 256 + threadIdx.x;       // 8*2*256*1024
    int n  = idx & 1023;
    int t  = idx >> 10;
    int k2 = t & 255;
    int z  = t >> 8;
    int b = z >> 1, net = z & 1;
    int k = 2 * k2;
    const float* BG = net ? p_bg : g_bg;
    const float* BB = net ? p_bb : g_bb;
    const float* BM = net ? p_bm : g_bm;
    const float* BV = net ? p_bv : g_bv;
    float sc0 = BG[k] * rsqrtf(BV[k] + 1e-5f);
    float sh0 = BB[k] - BM[k] * sc0;
    float sc1 = BG[k + 1] * rsqrtf(BV[k + 1] + 1e-5f);
    float sh1 = BB[k + 1] - BM[k + 1] * sc1;
    const float* src = d_X + ((size_t)b * 1024 + net * 512 + k) * NEDGE + n;
    float v0 = fmaxf(src[0] * sc0 + sh0, 0.f);
    float v1 = fmaxf(src[NEDGE] * sc1 + sh1, 0.f);
    split_pair(v0, v1, d_Xph[idx], d_Xpl[idx]);
}

// ---------------- HMMA GEMM, cp.async double-buffered ----------------
// MODE 0 (intro, unique cols): X[i*32+j] and X[j*32+i] scattered  (NTOT=640)
// MODE 1 (chorus): Y = D + X + cb                                  (NTOT=1024)
// MODE 2 (node):   GnP partials                                    (NTOT=256, z = k-split)
template<int K2TOT, int NTOT, int MODE>
__global__ void __launch_bounds__(256, 2) gemm_mma(
    const uint32_t* __restrict__ Ah_g, const uint32_t* __restrict__ Al_g,
    const uint32_t* __restrict__ Bh_g, const uint32_t* __restrict__ Bl_g,
    const float* __restrict__ g_cb, const float* __restrict__ p_cb)
{
    extern __shared__ uint32_t smw[];
    const uint32_t sbase = smem_u32(smw);

    const int tid  = threadIdx.x;
    const int lane = tid & 31, wid = tid >> 5;
    const int wm = wid >> 2, wn = wid & 3;
    const int b    = blockIdx.z;
    const int row0 = blockIdx.y * 128;
    const int col0 = blockIdx.x * 128;
    const int net  = (row0 >> 9) & 1;

    const uint32_t* Ah = Ah_g + (size_t)row0 * K2TOT;
    const uint32_t* Al = Al_g + (size_t)row0 * K2TOT;
    const int bz = (MODE == 0) ? b : (MODE == 1 ? b * 2 + net : 0);
    const uint32_t* Bh = Bh_g + (size_t)bz * K2TOT * NTOT + col0;
    const uint32_t* Bl = Bl_g + (size_t)bz * K2TOT * NTOT + col0;

    constexpr int NCH = K2TOT / 16;
    constexpr int CHUNKS = (MODE == 2) ? NCH / 4 : NCH;
    const int kc0 = (MODE == 2) ? blockIdx.z * CHUNKS : 0;

    #define PREFETCH(kc, bufw) do { \
        _Pragma("unroll") \
        for (int i = 0; i < 2; i++) { \
            int t = tid + i * 256; \
            int row = t >> 2, seg = t & 3; \
            size_t go = (size_t)row * K2TOT + (kc) * 16 + seg * 4; \
            cpa16(sbase + ((bufw) + AH_O + row * 20 + seg * 4) * 4, Ah + go); \
            cpa16(sbase + ((bufw) + AL_O + row * 20 + seg * 4) * 4, Al + go); \
            int brow = t >> 5, bseg = t & 31; \
            size_t gb = (size_t)((kc) * 16 + brow) * NTOT + bseg * 4; \
            cpa16(sbase + ((bufw) + BH_O + brow * 136 + bseg * 4) * 4, Bh + gb); \
            cpa16(sbase + ((bufw) + BL_O + brow * 136 + bseg * 4) * 4, Bl + gb); \
        } \
        asm volatile("cp.async.commit_group;" ::: "memory"); \
    } while (0)

    float acc[4][4][4];
    #pragma unroll
    for (int i = 0; i < 4; i++)
        #pragma unroll
        for (int j = 0; j < 4; j++)
            #pragma unroll
            for (int v = 0; v < 4; v++) acc[i][j][v] = 0.f;

    PREFETCH(kc0, 0);

    #pragma unroll 1
    for (int ci = 0; ci < CHUNKS; ci++) {
        const int bufw = (ci & 1) * BUF_WORDS;
        if (ci + 1 < CHUNKS) {
            PREFETCH(kc0 + ci + 1, ((ci + 1) & 1) * BUF_WORDS);
            asm volatile("cp.async.wait_group 1;" ::: "memory");
        } else {
            asm volatile("cp.async.wait_group 0;" ::: "memory");
        }
        __syncthreads();

        const uint32_t* AhS = smw + bufw + AH_O;
        const uint32_t* AlS = smw + bufw + AL_O;
        const uint32_t* BhS = smw + bufw + BH_O;
        const uint32_t* BlS = smw + bufw + BL_O;

        #pragma unroll
        for (int s = 0; s < 2; s++) {
            const int k2a = s * 8 + (lane & 3);
            uint32_t bh[4][2], bl[4][2];
            #pragma unroll
            for (int nf = 0; nf < 4; nf++) {
                int n = wn * 32 + nf * 8 + (lane >> 2);
                bh[nf][0] = BhS[k2a * 136 + n];
                bh[nf][1] = BhS[(k2a + 4) * 136 + n];
                bl[nf][0] = BlS[k2a * 136 + n];
                bl[nf][1] = BlS[(k2a + 4) * 136 + n];
            }
            #pragma unroll
            for (int mf = 0; mf < 4; mf++) {
                int row = wm * 64 + mf * 16 + (lane >> 2);
                uint32_t ah[4], al[4];
                ah[0] = AhS[row * 20 + k2a];       ah[1] = AhS[(row + 8) * 20 + k2a];
                ah[2] = AhS[row * 20 + k2a + 4];   ah[3] = AhS[(row + 8) * 20 + k2a + 4];
                al[0] = AlS[row * 20 + k2a];       al[1] = AlS[(row + 8) * 20 + k2a];
                al[2] = AlS[row * 20 + k2a + 4];   al[3] = AlS[(row + 8) * 20 + k2a + 4];
                #pragma unroll
                for (int nf = 0; nf < 4; nf++) {
                    mma16816(acc[mf][nf], ah, bh[nf]);
                    mma16816(acc[mf][nf], ah, bl[nf]);
                    mma16816(acc[mf][nf], al, bh[nf]);
                }
            }
        }
        __syncthreads();
    }
    #undef PREFETCH

    // ---- epilogue ----
    #pragma unroll
    for (int mf = 0; mf < 4; mf++) {
        int row_g = row0 + wm * 64 + mf * 16 + (lane >> 2);
        #pragma unroll
        for (int nf = 0; nf < 4; nf++) {
            int colg = col0 + wn * 32 + nf * 8 + (lane & 3) * 2;
            float* a = acc[mf][nf];
            if (MODE == 2) {
                int bb = colg >> 5, p = colg & 31;
                float* dst = d_GnP + (((size_t)blockIdx.z * 8 + bb) * 2048) * NPT;
                *(float2*)&dst[(size_t)row_g * NPT + p] = make_float2(a[0], a[1]);
                *(float2*)&dst[(size_t)(row_g + 8) * NPT + p] = make_float2(a[2], a[3]);
            } else if (MODE == 0) {
                // scatter unique column c to (i,j) and (j,i)
                int r = row_g & 511;
                size_t gir = (size_t)(b * 2048 + net * 1024 + r);
                #pragma unroll
                for (int e = 0; e < 4; e++) {
                    int c = colg + (e & 1);
                    if (c >= NPAIR) continue;
                    int rr = row_g + (e >> 1) * 8;
                    size_t gi = (gir + (e >> 1) * 8) * NPT;
                    size_t gj = gi + 512 * NPT;
                    int ii = d_pi[c], jj = d_pj[c];
                    size_t obase = ((size_t)b * 1024 + rr) * NEDGE;
                    float v = a[e];
                    d_X[obase + ii * 32 + jj] = v + d_Gn[gi + ii] + d_Gn[gj + jj];
                    if (ii != jj)
                        d_X[obase + jj * 32 + ii] = v + d_Gn[gi + jj] + d_Gn[gj + ii];
                }
            } else {
                size_t obase = ((size_t)b * 1024 + row_g) * NEDGE;
                int r = row_g & 511;
                const float* CB = net ? p_cb : g_cb;
                float cb0 = CB[r], cb8 = CB[r + 8];
                float2 x0 = *(const float2*)&d_X[obase + colg];
                float2 x1 = *(const float2*)&d_X[obase + 8 * NEDGE + colg];
                float2 w0 = make_float2(a[0] + x0.x + cb0, a[1] + x0.y + cb0);
                float2 w1 = make_float2(a[2] + x1.x + cb8, a[3] + x1.y + cb8);
                *(float2*)&d_Y[obase + colg] = w0;
                *(float2*)&d_Y[obase + 8 * NEDGE + colg] = w1;
            }
        }
    }
}

// ---------------- reduce node partials + bias ----------------
__global__ void reduceGn(const float* __restrict__ g_ib, const float* __restrict__ p_ib)
{
    int idx = blockIdx.x * 256 + threadIdx.x;   // 8*2048*32
    int r = (idx >> 5) & 2047;
    float bias = (r < 512) ? g_ib[r] : ((r >= 1024 && r < 1536) ? p_ib[r - 1024] : 0.f);
    float s = bias;
    #pragma unroll
    for (int z = 0; z < 4; z++)
        s += d_GnP[(size_t)z * (8 * 2048 * NPT) + idx];
    d_Gn[idx] = s;
}

// ---------------- K5: outro (Y streamed once, all 65 oc in regs) ----------------
__global__ void __launch_bounds__(128) outro_kernel(const float* __restrict__ g_ow,
                                                    const float* __restrict__ p_ow)
{
    __shared__ float wg[128];
    __shared__ float wp[64 * 128];
    const int tx = threadIdx.x;
    const int m  = blockIdx.x * 128 + tx;
    const int b  = blockIdx.y;
    const int rz = blockIdx.z;       // k-split 0..3
    const int r0 = rz * 128;

    wg[tx] = g_ow[r0 + tx];
    for (int i = tx; i < 64 * 128; i += 128) {
        int oc = i >> 7, r = i & 127;
        wp[i] = p_ow[(size_t)oc * 512 + r0 + r];
    }
    __syncthreads();

    float accg = 0.f;
    float acc[64];
    #pragma unroll
    for (int oc = 0; oc < 64; oc++) acc[oc] = 0.f;

    const float* Yg = d_Y + ((size_t)b * 1024 + r0) * NEDGE + m;
    const float* Yp = Yg + (size_t)512 * NEDGE;
    #pragma unroll 4
    for (int r = 0; r < 128; r++) {
        float yg = Yg[(size_t)r * NEDGE];
        float yp = Yp[(size_t)r * NEDGE];
        accg += wg[r] * yg;
        #pragma unroll
        for (int oc = 0; oc < 64; oc++)
            acc[oc] += wp[oc * 128 + r] * yp;
    }

    d_gateP[((size_t)rz * 8 + b) * NEDGE + m] = accg;
    float* dst = d_prP + ((size_t)rz * 8 + b) * 64 * NEDGE + m;
    #pragma unroll
    for (int oc = 0; oc < 64; oc++)
        dst[(size_t)oc * NEDGE] = acc[oc];
}

// ---------------- K6: final ----------------
__global__ void final_kernel(const int* __restrict__ nvec,
                             const float* __restrict__ g_ob, const float* __restrict__ p_ob,
                             float* __restrict__ out)
{
    const int m = blockIdx.x * blockDim.x + threadIdx.x;
    const int b = blockIdx.y;
    if (m >= NEDGE) return;
    const int i = m >> 5, j = m & 31;
    const int nb = nvec[b];
    const bool ok = (i < nb) && (j < nb);

    float gsum = g_ob[0];
    #pragma unroll
    for (int z = 0; z < 4; z++)
        gsum += d_gateP[((size_t)z * 8 + b) * NEDGE + m];

    float pv[64];
    float ss = 0.f;
    #pragma unroll
    for (int c = 0; c < 64; c++) {
        float v = p_ob[c];
        #pragma unroll
        for (int z = 0; z < 4; z++)
            v += d_prP[(((size_t)z * 8 + b) * 64 + c) * NEDGE + m];
        pv[c] = v;
        ss += v * v;
    }
    float g = 1.f / (1.f + expf(-gsum));
    float s = ok ? (g / fmaxf(sqrtf(ss), 1e-12f)) : 0.f;

    #pragma unroll
    for (int c = 0; c < 64; c++)
        out[((size_t)b * 64 + c) * NEDGE + m] = pv[c] * s;
}

// ---------------- launch ----------------
extern "C" void kernel_launch(void* const* d_in, const int* in_sizes, int n_in,
                              void* d_out, int out_size)
{
    const float* f0 = (const float*)d_in[0];
    const float* f1 = (const float*)d_in[1];
    const float* f2 = (const float*)d_in[2];
    const float* f3 = (const float*)d_in[3];
    const float* f4 = (const float*)d_in[4];
    const float* f5 = (const float*)d_in[5];
    const float* P  = (const float*)d_in[6];
    const int*   nv = (const int*)d_in[7];
    const float* g_iw = (const float*)d_in[8];
    const float* g_ib = (const float*)d_in[9];
    const float* g_bg = (const float*)d_in[10];
    const float* g_bb = (const float*)d_in[11];
    const float* g_bm = (const float*)d_in[12];
    const float* g_bv = (const float*)d_in[13];
    const float* g_cw = (const float*)d_in[14];
    const float* g_cb = (const float*)d_in[15];
    const float* g_ow = (const float*)d_in[16];
    const float* g_ob = (const float*)d_in[17];
    const float* p_iw = (const float*)d_in[18];
    const float* p_ib = (const float*)d_in[19];
    const float* p_bg = (const float*)d_in[20];
    const float* p_bb = (const float*)d_in[21];
    const float* p_bm = (const float*)d_in[22];
    const float* p_bv = (const float*)d_in[23];
    const float* p_cw = (const float*)d_in[24];
    const float* p_cb = (const float*)d_in[25];
    const float* p_ow = (const float*)d_in[26];
    const float* p_ob = (const float*)d_in[27];
    float* out = (float*)d_out;

    cudaFuncSetAttribute(gemm_mma<768, NECOL, 0>, cudaFuncAttributeMaxDynamicSharedMemorySize, GEMM_SMEM_BYTES);
    cudaFuncSetAttribute(gemm_mma<256, 1024, 1>,  cudaFuncAttributeMaxDynamicSharedMemorySize, GEMM_SMEM_BYTES);
    cudaFuncSetAttribute(gemm_mma<768, 256, 2>,   cudaFuncAttributeMaxDynamicSharedMemorySize, GEMM_SMEM_BYTES);

    uint32_t *pWIh, *pWIl, *pCWh, *pCWl, *pWNh, *pWNl, *pEph, *pEpl, *pFnh, *pFnl, *pXph, *pXpl;
    cudaGetSymbolAddress((void**)&pWIh, d_WIh);
    cudaGetSymbolAddress((void**)&pWIl, d_WIl);
    cudaGetSymbolAddress((void**)&pCWh, d_CWh);
    cudaGetSymbolAddress((void**)&pCWl, d_CWl);
    cudaGetSymbolAddress((void**)&pWNh, d_WNh);
    cudaGetSymbolAddress((void**)&pWNl, d_WNl);
    cudaGetSymbolAddress((void**)&pEph, d_Eph);
    cudaGetSymbolAddress((void**)&pEpl, d_Epl);
    cudaGetSymbolAddress((void**)&pFnh, d_Fnh);
    cudaGetSymbolAddress((void**)&pFnl, d_Fnl);
    cudaGetSymbolAddress((void**)&pXph, d_Xph);
    cudaGetSymbolAddress((void**)&pXpl, d_Xpl);

    init_pairs<<<(NPAIR + 63) / 64, 64>>>();
    align_kernel<<<dim3((NPTS + 31) / 32, BSZ), dim3(32, 8)>>>(f0, f1, f2, f3, f4, f5, P);
    convWI<<<(2 * 512 * 768) / 256, 256>>>(g_iw, p_iw);
    convWC<<<(2 * 512 * 256) / 256, 256>>>(g_cw, p_cw);
    convWN<<<(2048 * 768) / 256, 256>>>(g_iw, p_iw);
    convF <<<(768 * 256) / 256, 256>>>();
    convE <<<(BSZ * 768 * NECOL) / 256, 256>>>();

    gemm_mma<768, 256, 2><<<dim3(2, 16, 4), 256, GEMM_SMEM_BYTES>>>(
        pWNh, pWNl, pFnh, pFnl, nullptr, nullptr);
    reduceGn<<<(BSZ * 2048 * NPT) / 256, 256>>>(g_ib, p_ib);

    gemm_mma<768, NECOL, 0><<<dim3(5, 8, BSZ), 256, GEMM_SMEM_BYTES>>>(
        pWIh, pWIl, pEph, pEpl, nullptr, nullptr);

    convX<<<(BSZ * 2 * 256 * 1024) / 256, 256>>>(g_bg, g_bb, g_bm, g_bv,
                                                 p_bg, p_bb, p_bm, p_bv);

    gemm_mma<256, 1024, 1><<<dim3(8, 8, BSZ), 256, GEMM_SMEM_BYTES>>>(
        pCWh, pCWl, pXph, pXpl, g_cb, p_cb);

    outro_kernel<<<dim3(8, BSZ, 4), 128>>>(g_ow, p_ow);
    final_kernel<<<dim3(4, BSZ), 256>>>(nv, g_ob, p_ob, out);
}

// round 10
// speedup vs baseline: 2.8325x; 1.1070x over previous
#include <cuda_runtime.h>
#include <cuda_bf16.h>
#include <math.h>
#include <stdint.h>

// ---------------- problem constants ----------------
#define BSZ   8
#define NPT   32
#define NEDGE 1024
#define NPAIR 528            // unique (i<=j) midpoint pairs
#define NECOL 640            // padded unique-E columns (5 x 128)
#define NPTS  560            // 32 nodes + 528 unique midpoints
#define LATC  1536

// ---------------- gemm smem layout (u32 words) ----------------
#define A_WORDS (128 * 20)
#define B_WORDS (16 * 136)
#define BUF_WORDS (2 * A_WORDS + 2 * B_WORDS)
#define AH_O 0
#define AL_O A_WORDS
#define BH_O (2 * A_WORDS)
#define BL_O (2 * A_WORDS + B_WORDS)
#define GEMM_SMEM_BYTES (2 * BUF_WORDS * 4)       // 75776 B

// ---------------- scratch (__device__ globals) ----------------
__device__ float d_A [BSZ * LATC * NPTS];
__device__ float d_Gn[BSZ * 2048 * NPT];
__device__ float d_GnP[4 * BSZ * 2048 * NPT];
__device__ float d_X [BSZ * 1024 * NEDGE];
__device__ float d_Y [BSZ * 1024 * NEDGE];
__device__ float d_gateP[4 * BSZ * NEDGE];
__device__ float d_prP [4 * BSZ * 64 * NEDGE];
__device__ int   d_pi[NPAIR];
__device__ int   d_pj[NPAIR];

// packed bf16 k-pair operands
__device__ __align__(16) uint32_t d_WIh[2 * 512 * 768];
__device__ __align__(16) uint32_t d_WIl[2 * 512 * 768];
__device__ __align__(16) uint32_t d_CWh[2 * 512 * 256];
__device__ __align__(16) uint32_t d_CWl[2 * 512 * 256];
__device__ __align__(16) uint32_t d_WNh[2048 * 768];
__device__ __align__(16) uint32_t d_WNl[2048 * 768];
__device__ __align__(16) uint32_t d_Eph[BSZ * 768 * NECOL];
__device__ __align__(16) uint32_t d_Epl[BSZ * 768 * NECOL];
__device__ __align__(16) uint32_t d_Fnh[768 * 256];
__device__ __align__(16) uint32_t d_Fnl[768 * 256];
__device__ __align__(16) uint32_t d_Xph[BSZ * 2 * 256 * 1024];
__device__ __align__(16) uint32_t d_Xpl[BSZ * 2 * 256 * 1024];

// ---------------- helpers ----------------
__device__ __forceinline__ void split_pair(float x, float y, uint32_t& hp, uint32_t& lp) {
    __nv_bfloat16 hx = __float2bfloat16_rn(x), hy = __float2bfloat16_rn(y);
    __nv_bfloat16 lx = __float2bfloat16_rn(x - __bfloat162float(hx));
    __nv_bfloat16 ly = __float2bfloat16_rn(y - __bfloat162float(hy));
    __nv_bfloat162 h2(hx, hy), l2(lx, ly);
    hp = *reinterpret_cast<uint32_t*>(&h2);
    lp = *reinterpret_cast<uint32_t*>(&l2);
}

__device__ __forceinline__ void mma16816(float* c, const uint32_t* a, const uint32_t* b) {
    asm volatile("mma.sync.aligned.m16n8k16.row.col.f32.bf16.bf16.f32 "
                 "{%0,%1,%2,%3}, {%4,%5,%6,%7}, {%8,%9}, {%0,%1,%2,%3};"
                 : "+f"(c[0]), "+f"(c[1]), "+f"(c[2]), "+f"(c[3])
                 : "r"(a[0]), "r"(a[1]), "r"(a[2]), "r"(a[3]),
                   "r"(b[0]), "r"(b[1]));
}

__device__ __forceinline__ uint32_t smem_u32(const void* p) {
    uint32_t a;
    asm("{ .reg .u64 t; cvta.to.shared.u64 t, %1; cvt.u32.u64 %0, t; }" : "=r"(a) : "l"(p));
    return a;
}
__device__ __forceinline__ void cpa16(uint32_t dst_s, const void* src) {
    asm volatile("cp.async.cg.shared.global [%0], [%1], 16;" :: "r"(dst_s), "l"(src));
}

// closed-form pair decode: pc in [0,528) -> (i, j) with i<=j
__device__ __forceinline__ void pair_decode(int pc, int& i, int& j) {
    float s = sqrtf(4225.0f - 8.0f * (float)pc);
    i = (int)((65.0f - s) * 0.5f);
    int base = 32 * i - ((i * (i - 1)) >> 1);
    if (pc < base) { i--; base = 32 * i - ((i * (i - 1)) >> 1); }
    else { int nxt = base + (32 - i); if (pc >= nxt) { i++; base = nxt; } }
    j = i + (pc - base);
}

// ---------------- K1: flattened bilinear align (one thread per output) ----------------
__global__ void align_kernel(const float* __restrict__ f0, const float* __restrict__ f1,
                             const float* __restrict__ f2, const float* __restrict__ f3,
                             const float* __restrict__ f4, const float* __restrict__ f5,
                             const float* __restrict__ P)
{
    int idx = blockIdx.x * 256 + threadIdx.x;       // 8 * 1536 * 560
    if (idx >= BSZ * LATC * NPTS) return;
    int pid = idx % NPTS;
    int t   = idx / NPTS;
    int c   = t % LATC;
    int b   = t / LATC;

    float px, py;
    if (pid < NPT) {
        px = P[(b * NPT + pid) * 2 + 0];
        py = P[(b * NPT + pid) * 2 + 1];
    } else {
        int i, j;
        pair_decode(pid - NPT, i, j);
        px = 0.5f * (P[(b * NPT + i) * 2 + 0] + P[(b * NPT + j) * 2 + 0]);
        py = 0.5f * (P[(b * NPT + i) * 2 + 1] + P[(b * NPT + j) * 2 + 1]);
    }

    const float* f; int choff, H, C;
    if      (c < 64)   { f = f0; choff = 0;    H = 128; C = 64;  }
    else if (c < 128)  { f = f1; choff = 64;   H = 64;  C = 64;  }
    else if (c < 256)  { f = f2; choff = 128;  H = 32;  C = 128; }
    else if (c < 512)  { f = f3; choff = 256;  H = 16;  C = 256; }
    else if (c < 1024) { f = f4; choff = 512;  H = 8;   C = 512; }
    else               { f = f5; choff = 1024; H = 1;   C = 512; }

    float xs = fminf(fmaxf(px * ((float)H * (1.0f / 256.0f)) - 0.5f, 0.0f), (float)(H - 1));
    float ys = fminf(fmaxf(py * ((float)H * (1.0f / 256.0f)) - 0.5f, 0.0f), (float)(H - 1));
    float x0f = floorf(xs), y0f = floorf(ys);
    float wx = xs - x0f, wy = ys - y0f;
    int x0 = (int)x0f, y0 = (int)y0f;
    int x1 = min(x0 + 1, H - 1), y1 = min(y0 + 1, H - 1);
    float w00 = (1.f - wx) * (1.f - wy);
    float w01 = wx * (1.f - wy);
    float w10 = (1.f - wx) * wy;
    float w11 = wx * wy;
    const float* base = f + (size_t)(b * C + (c - choff)) * (H * H);
    float v = base[y0 * H + x0] * w00 + base[y0 * H + x1] * w01
            + base[y1 * H + x0] * w10 + base[y1 * H + x1] * w11;
    d_A[idx] = v;
}

// ---------------- merged weight conversion (WI + WC + WN) + pair table ----------------
#define NWI (2 * 512 * 768)
#define NWC (2 * 512 * 256)
#define NWN (2048 * 768)
__global__ void convW(const float* __restrict__ g_iw, const float* __restrict__ p_iw,
                      const float* __restrict__ g_cw, const float* __restrict__ p_cw)
{
    int idx = blockIdx.x * 256 + threadIdx.x;
    if (idx < NPAIR) {
        int i, j;
        pair_decode(idx, i, j);
        d_pi[idx] = i; d_pj[idx] = j;
    }
    if (idx < NWI) {
        int k2 = idx % 768;
        int r  = (idx / 768) & 511;
        int net = idx / (512 * 768);
        const float* w = (net ? p_iw : g_iw) + (size_t)r * 4608 + 3072 + 2 * k2;
        split_pair(w[0], w[1], d_WIh[idx], d_WIl[idx]);
    } else if (idx < NWI + NWC) {
        int q = idx - NWI;
        int k2 = q & 255;
        int r  = (q >> 8) & 511;
        int net = q >> 17;
        const float* w = (net ? p_cw : g_cw) + (size_t)r * 512 + 2 * k2;
        split_pair(w[0], w[1], d_CWh[q], d_CWl[q]);
    } else if (idx < NWI + NWC + NWN) {
        int q = idx - NWI - NWC;
        int k2 = q % 768;
        int r  = q / 768;
        int part = r >> 9;
        const float* w = (part >= 2 ? p_iw : g_iw) + (size_t)(r & 511) * 4608
                         + ((part & 1) ? 1536 : 0) + 2 * k2;
        split_pair(w[0], w[1], d_WNh[q], d_WNl[q]);
    }
}

// ---------------- merged feature conversion (F + E) ----------------
#define NFC (768 * 256)
#define NEC (BSZ * 768 * NECOL)
__global__ void convFE()
{
    int idx = blockIdx.x * 256 + threadIdx.x;
    if (idx < NFC) {
        int n  = idx & 255;
        int k2 = idx >> 8;
        int b = n >> 5, p = n & 31;
        const float* src = d_A + ((size_t)b * LATC + 2 * k2) * NPTS + p;
        split_pair(src[0], src[NPTS], d_Fnh[idx], d_Fnl[idx]);
    } else if (idx < NFC + NEC) {
        int q = idx - NFC;
        int n  = q % NECOL;
        int t  = q / NECOL;
        int k2 = t % 768;
        int b  = t / 768;
        if (n >= NPAIR) { d_Eph[q] = 0u; d_Epl[q] = 0u; return; }
        const float* src = d_A + ((size_t)b * LATC + 2 * k2) * NPTS + NPT + n;
        split_pair(src[0], src[NPTS], d_Eph[q], d_Epl[q]);
    }
}

__global__ void convX(const float* __restrict__ g_bg, const float* __restrict__ g_bb,
                      const float* __restrict__ g_bm, const float* __restrict__ g_bv,
                      const float* __restrict__ p_bg, const float* __restrict__ p_bb,
                      const float* __restrict__ p_bm, const float* __restrict__ p_bv)
{
    int idx = blockIdx.x * 256 + threadIdx.x;       // 8*2*256*1024
    int n  = idx & 1023;
    int t  = idx >> 10;
    int k2 = t & 255;
    int z  = t >> 8;
    int b = z >> 1, net = z & 1;
    int k = 2 * k2;
    const float* BG = net ? p_bg : g_bg;
    const float* BB = net ? p_bb : g_bb;
    const float* BM = net ? p_bm : g_bm;
    const float* BV = net ? p_bv : g_bv;
    float sc0 = BG[k] * rsqrtf(BV[k] + 1e-5f);
    float sh0 = BB[k] - BM[k] * sc0;
    float sc1 = BG[k + 1] * rsqrtf(BV[k + 1] + 1e-5f);
    float sh1 = BB[k + 1] - BM[k + 1] * sc1;
    const float* src = d_X + ((size_t)b * 1024 + net * 512 + k) * NEDGE + n;
    float v0 = fmaxf(src[0] * sc0 + sh0, 0.f);
    float v1 = fmaxf(src[NEDGE] * sc1 + sh1, 0.f);
    split_pair(v0, v1, d_Xph[idx], d_Xpl[idx]);
}

// ---------------- HMMA GEMM, cp.async double-buffered ----------------
// MODE 0 (intro, unique cols -> symmetric scatter), MODE 1 (chorus), MODE 2 (node k-split)
template<int K2TOT, int NTOT, int MODE>
__global__ void __launch_bounds__(256, 2) gemm_mma(
    const uint32_t* __restrict__ Ah_g, const uint32_t* __restrict__ Al_g,
    const uint32_t* __restrict__ Bh_g, const uint32_t* __restrict__ Bl_g,
    const float* __restrict__ g_cb, const float* __restrict__ p_cb)
{
    extern __shared__ uint32_t smw[];
    const uint32_t sbase = smem_u32(smw);

    const int tid  = threadIdx.x;
    const int lane = tid & 31, wid = tid >> 5;
    const int wm = wid >> 2, wn = wid & 3;
    const int b    = blockIdx.z;
    const int row0 = blockIdx.y * 128;
    const int col0 = blockIdx.x * 128;
    const int net  = (row0 >> 9) & 1;

    const uint32_t* Ah = Ah_g + (size_t)row0 * K2TOT;
    const uint32_t* Al = Al_g + (size_t)row0 * K2TOT;
    const int bz = (MODE == 0) ? b : (MODE == 1 ? b * 2 + net : 0);
    const uint32_t* Bh = Bh_g + (size_t)bz * K2TOT * NTOT + col0;
    const uint32_t* Bl = Bl_g + (size_t)bz * K2TOT * NTOT + col0;

    constexpr int NCH = K2TOT / 16;
    constexpr int CHUNKS = (MODE == 2) ? NCH / 4 : NCH;
    const int kc0 = (MODE == 2) ? blockIdx.z * CHUNKS : 0;

    #define PREFETCH(kc, bufw) do { \
        _Pragma("unroll") \
        for (int i = 0; i < 2; i++) { \
            int t = tid + i * 256; \
            int row = t >> 2, seg = t & 3; \
            size_t go = (size_t)row * K2TOT + (kc) * 16 + seg * 4; \
            cpa16(sbase + ((bufw) + AH_O + row * 20 + seg * 4) * 4, Ah + go); \
            cpa16(sbase + ((bufw) + AL_O + row * 20 + seg * 4) * 4, Al + go); \
            int brow = t >> 5, bseg = t & 31; \
            size_t gb = (size_t)((kc) * 16 + brow) * NTOT + bseg * 4; \
            cpa16(sbase + ((bufw) + BH_O + brow * 136 + bseg * 4) * 4, Bh + gb); \
            cpa16(sbase + ((bufw) + BL_O + brow * 136 + bseg * 4) * 4, Bl + gb); \
        } \
        asm volatile("cp.async.commit_group;" ::: "memory"); \
    } while (0)

    float acc[4][4][4];
    #pragma unroll
    for (int i = 0; i < 4; i++)
        #pragma unroll
        for (int j = 0; j < 4; j++)
            #pragma unroll
            for (int v = 0; v < 4; v++) acc[i][j][v] = 0.f;

    PREFETCH(kc0, 0);

    #pragma unroll 1
    for (int ci = 0; ci < CHUNKS; ci++) {
        const int bufw = (ci & 1) * BUF_WORDS;
        if (ci + 1 < CHUNKS) {
            PREFETCH(kc0 + ci + 1, ((ci + 1) & 1) * BUF_WORDS);
            asm volatile("cp.async.wait_group 1;" ::: "memory");
        } else {
            asm volatile("cp.async.wait_group 0;" ::: "memory");
        }
        __syncthreads();

        const uint32_t* AhS = smw + bufw + AH_O;
        const uint32_t* AlS = smw + bufw + AL_O;
        const uint32_t* BhS = smw + bufw + BH_O;
        const uint32_t* BlS = smw + bufw + BL_O;

        #pragma unroll
        for (int s = 0; s < 2; s++) {
            const int k2a = s * 8 + (lane & 3);
            uint32_t bh[4][2], bl[4][2];
            #pragma unroll
            for (int nf = 0; nf < 4; nf++) {
                int n = wn * 32 + nf * 8 + (lane >> 2);
                bh[nf][0] = BhS[k2a * 136 + n];
                bh[nf][1] = BhS[(k2a + 4) * 136 + n];
                bl[nf][0] = BlS[k2a * 136 + n];
                bl[nf][1] = BlS[(k2a + 4) * 136 + n];
            }
            #pragma unroll
            for (int mf = 0; mf < 4; mf++) {
                int row = wm * 64 + mf * 16 + (lane >> 2);
                uint32_t ah[4], al[4];
                ah[0] = AhS[row * 20 + k2a];       ah[1] = AhS[(row + 8) * 20 + k2a];
                ah[2] = AhS[row * 20 + k2a + 4];   ah[3] = AhS[(row + 8) * 20 + k2a + 4];
                al[0] = AlS[row * 20 + k2a];       al[1] = AlS[(row + 8) * 20 + k2a];
                al[2] = AlS[row * 20 + k2a + 4];   al[3] = AlS[(row + 8) * 20 + k2a + 4];
                #pragma unroll
                for (int nf = 0; nf < 4; nf++) {
                    mma16816(acc[mf][nf], ah, bh[nf]);
                    mma16816(acc[mf][nf], ah, bl[nf]);
                    mma16816(acc[mf][nf], al, bh[nf]);
                }
            }
        }
        __syncthreads();
    }
    #undef PREFETCH

    // ---- epilogue ----
    #pragma unroll
    for (int mf = 0; mf < 4; mf++) {
        int row_g = row0 + wm * 64 + mf * 16 + (lane >> 2);
        #pragma unroll
        for (int nf = 0; nf < 4; nf++) {
            int colg = col0 + wn * 32 + nf * 8 + (lane & 3) * 2;
            float* a = acc[mf][nf];
            if (MODE == 2) {
                int bb = colg >> 5, p = colg & 31;
                float* dst = d_GnP + (((size_t)blockIdx.z * 8 + bb) * 2048) * NPT;
                *(float2*)&dst[(size_t)row_g * NPT + p] = make_float2(a[0], a[1]);
                *(float2*)&dst[(size_t)(row_g + 8) * NPT + p] = make_float2(a[2], a[3]);
            } else if (MODE == 0) {
                int r = row_g & 511;
                size_t gir = (size_t)(b * 2048 + net * 1024 + r);
                #pragma unroll
                for (int e = 0; e < 4; e++) {
                    int c = colg + (e & 1);
                    if (c >= NPAIR) continue;
                    int rr = row_g + (e >> 1) * 8;
                    size_t gi = (gir + (e >> 1) * 8) * NPT;
                    size_t gj = gi + 512 * NPT;
                    int ii = d_pi[c], jj = d_pj[c];
                    size_t obase = ((size_t)b * 1024 + rr) * NEDGE;
                    float v = a[e];
                    d_X[obase + ii * 32 + jj] = v + d_Gn[gi + ii] + d_Gn[gj + jj];
                    if (ii != jj)
                        d_X[obase + jj * 32 + ii] = v + d_Gn[gi + jj] + d_Gn[gj + ii];
                }
            } else {
                size_t obase = ((size_t)b * 1024 + row_g) * NEDGE;
                int r = row_g & 511;
                const float* CB = net ? p_cb : g_cb;
                float cb0 = CB[r], cb8 = CB[r + 8];
                float2 x0 = *(const float2*)&d_X[obase + colg];
                float2 x1 = *(const float2*)&d_X[obase + 8 * NEDGE + colg];
                float2 w0 = make_float2(a[0] + x0.x + cb0, a[1] + x0.y + cb0);
                float2 w1 = make_float2(a[2] + x1.x + cb8, a[3] + x1.y + cb8);
                *(float2*)&d_Y[obase + colg] = w0;
                *(float2*)&d_Y[obase + 8 * NEDGE + colg] = w1;
            }
        }
    }
}

// ---------------- reduce node partials + bias ----------------
__global__ void reduceGn(const float* __restrict__ g_ib, const float* __restrict__ p_ib)
{
    int idx = blockIdx.x * 256 + threadIdx.x;   // 8*2048*32
    int r = (idx >> 5) & 2047;
    float bias = (r < 512) ? g_ib[r] : ((r >= 1024 && r < 1536) ? p_ib[r - 1024] : 0.f);
    float s = bias;
    #pragma unroll
    for (int z = 0; z < 4; z++)
        s += d_GnP[(size_t)z * (8 * 2048 * NPT) + idx];
    d_Gn[idx] = s;
}

// ---------------- outro ----------------
__global__ void __launch_bounds__(128) outro_kernel(const float* __restrict__ g_ow,
                                                    const float* __restrict__ p_ow)
{
    __shared__ float wg[128];
    __shared__ float wp[64 * 128];
    const int tx = threadIdx.x;
    const int m  = blockIdx.x * 128 + tx;
    const int b  = blockIdx.y;
    const int rz = blockIdx.z;
    const int r0 = rz * 128;

    wg[tx] = g_ow[r0 + tx];
    for (int i = tx; i < 64 * 128; i += 128) {
        int oc = i >> 7, r = i & 127;
        wp[i] = p_ow[(size_t)oc * 512 + r0 + r];
    }
    __syncthreads();

    float accg = 0.f;
    float acc[64];
    #pragma unroll
    for (int oc = 0; oc < 64; oc++) acc[oc] = 0.f;

    const float* Yg = d_Y + ((size_t)b * 1024 + r0) * NEDGE + m;
    const float* Yp = Yg + (size_t)512 * NEDGE;
    #pragma unroll 4
    for (int r = 0; r < 128; r++) {
        float yg = Yg[(size_t)r * NEDGE];
        float yp = Yp[(size_t)r * NEDGE];
        accg += wg[r] * yg;
        #pragma unroll
        for (int oc = 0; oc < 64; oc++)
            acc[oc] += wp[oc * 128 + r] * yp;
    }

    d_gateP[((size_t)rz * 8 + b) * NEDGE + m] = accg;
    float* dst = d_prP + ((size_t)rz * 8 + b) * 64 * NEDGE + m;
    #pragma unroll
    for (int oc = 0; oc < 64; oc++)
        dst[(size_t)oc * NEDGE] = acc[oc];
}

// ---------------- final ----------------
__global__ void final_kernel(const int* __restrict__ nvec,
                             const float* __restrict__ g_ob, const float* __restrict__ p_ob,
                             float* __restrict__ out)
{
    const int m = blockIdx.x * blockDim.x + threadIdx.x;
    const int b = blockIdx.y;
    if (m >= NEDGE) return;
    const int i = m >> 5, j = m & 31;
    const int nb = nvec[b];
    const bool ok = (i < nb) && (j < nb);

    float gsum = g_ob[0];
    #pragma unroll
    for (int z = 0; z < 4; z++)
        gsum += d_gateP[((size_t)z * 8 + b) * NEDGE + m];

    float pv[64];
    float ss = 0.f;
    #pragma unroll
    for (int c = 0; c < 64; c++) {
        float v = p_ob[c];
        #pragma unroll
        for (int z = 0; z < 4; z++)
            v += d_prP[(((size_t)z * 8 + b) * 64 + c) * NEDGE + m];
        pv[c] = v;
        ss += v * v;
    }
    float g = 1.f / (1.f + expf(-gsum));
    float s = ok ? (g / fmaxf(sqrtf(ss), 1e-12f)) : 0.f;

    #pragma unroll
    for (int c = 0; c < 64; c++)
        out[((size_t)b * 64 + c) * NEDGE + m] = pv[c] * s;
}

// ---------------- launch ----------------
extern "C" void kernel_launch(void* const* d_in, const int* in_sizes, int n_in,
                              void* d_out, int out_size)
{
    const float* f0 = (const float*)d_in[0];
    const float* f1 = (const float*)d_in[1];
    const float* f2 = (const float*)d_in[2];
    const float* f3 = (const float*)d_in[3];
    const float* f4 = (const float*)d_in[4];
    const float* f5 = (const float*)d_in[5];
    const float* P  = (const float*)d_in[6];
    const int*   nv = (const int*)d_in[7];
    const float* g_iw = (const float*)d_in[8];
    const float* g_ib = (const float*)d_in[9];
    const float* g_bg = (const float*)d_in[10];
    const float* g_bb = (const float*)d_in[11];
    const float* g_bm = (const float*)d_in[12];
    const float* g_bv = (const float*)d_in[13];
    const float* g_cw = (const float*)d_in[14];
    const float* g_cb = (const float*)d_in[15];
    const float* g_ow = (const float*)d_in[16];
    const float* g_ob = (const float*)d_in[17];
    const float* p_iw = (const float*)d_in[18];
    const float* p_ib = (const float*)d_in[19];
    const float* p_bg = (const float*)d_in[20];
    const float* p_bb = (const float*)d_in[21];
    const float* p_bm = (const float*)d_in[22];
    const float* p_bv = (const float*)d_in[23];
    const float* p_cw = (const float*)d_in[24];
    const float* p_cb = (const float*)d_in[25];
    const float* p_ow = (const float*)d_in[26];
    const float* p_ob = (const float*)d_in[27];
    float* out = (float*)d_out;

    cudaFuncSetAttribute(gemm_mma<768, NECOL, 0>, cudaFuncAttributeMaxDynamicSharedMemorySize, GEMM_SMEM_BYTES);
    cudaFuncSetAttribute(gemm_mma<256, 1024, 1>,  cudaFuncAttributeMaxDynamicSharedMemorySize, GEMM_SMEM_BYTES);
    cudaFuncSetAttribute(gemm_mma<768, 256, 2>,   cudaFuncAttributeMaxDynamicSharedMemorySize, GEMM_SMEM_BYTES);

    uint32_t *pWIh, *pWIl, *pCWh, *pCWl, *pWNh, *pWNl, *pEph, *pEpl, *pFnh, *pFnl, *pXph, *pXpl;
    cudaGetSymbolAddress((void**)&pWIh, d_WIh);
    cudaGetSymbolAddress((void**)&pWIl, d_WIl);
    cudaGetSymbolAddress((void**)&pCWh, d_CWh);
    cudaGetSymbolAddress((void**)&pCWl, d_CWl);
    cudaGetSymbolAddress((void**)&pWNh, d_WNh);
    cudaGetSymbolAddress((void**)&pWNl, d_WNl);
    cudaGetSymbolAddress((void**)&pEph, d_Eph);
    cudaGetSymbolAddress((void**)&pEpl, d_Epl);
    cudaGetSymbolAddress((void**)&pFnh, d_Fnh);
    cudaGetSymbolAddress((void**)&pFnl, d_Fnl);
    cudaGetSymbolAddress((void**)&pXph, d_Xph);
    cudaGetSymbolAddress((void**)&pXpl, d_Xpl);

    // launch order: intro GEMM is the 6th launch (ncu -s 5 -c 1 profiles it)
    align_kernel<<<(BSZ * LATC * NPTS + 255) / 256, 256>>>(f0, f1, f2, f3, f4, f5, P);
    convW <<<(NWI + NWC + NWN + 255) / 256, 256>>>(g_iw, p_iw, g_cw, p_cw);
    convFE<<<(NFC + NEC + 255) / 256, 256>>>();

    gemm_mma<768, 256, 2><<<dim3(2, 16, 4), 256, GEMM_SMEM_BYTES>>>(
        pWNh, pWNl, pFnh, pFnl, nullptr, nullptr);
    reduceGn<<<(BSZ * 2048 * NPT) / 256, 256>>>(g_ib, p_ib);

    gemm_mma<768, NECOL, 0><<<dim3(5, 8, BSZ), 256, GEMM_SMEM_BYTES>>>(
        pWIh, pWIl, pEph, pEpl, nullptr, nullptr);

    convX<<<(BSZ * 2 * 256 * 1024) / 256, 256>>>(g_bg, g_bb, g_bm, g_bv,
                                                 p_bg, p_bb, p_bm, p_bv);

    gemm_mma<256, 1024, 1><<<dim3(8, 8, BSZ), 256, GEMM_SMEM_BYTES>>>(
        pCWh, pCWl, pXph, pXpl, g_cb, p_cb);

    outro_kernel<<<dim3(8, BSZ, 4), 128>>>(g_ow, p_ow);
    final_kernel<<<dim3(4, BSZ), 256>>>(nv, g_ob, p_ob, out);
}